// round 11
// baseline (speedup 1.0000x reference)
#include <cuda_runtime.h>
#include <cuda_bf16.h>
#include <cuda_pipeline_primitives.h>
#include <cstdio>
#include <cstdint>

#define NN 100000
#define EE 500000
#define GG 2000
#define LL 5
#define EMB 300
#define H2  600
#define FEATD 256
#define EPSV 1e-5f
#define SRCMASK 0x1FFFF

// ---------------- scratch (device globals; no allocs allowed) ----------------
__device__ float g_h[(size_t)NN * EMB];
__device__ float g_agg[(size_t)NN * EMB];
__device__ float g_hidden[(size_t)NN * H2];
__device__ float g_hf[(size_t)NN * FEATD];
__device__ float g_bnsum[EMB];
__device__ float g_bnsq[EMB];
__device__ float g_bnscale[EMB];
__device__ float g_bnshift[EMB];
__device__ float g_pool[(size_t)GG * FEATD];
__device__ float g_ctab[18 * EMB];
__device__ float g_wbuf[EMB * H2];     // K-major tf32-rounded weights [Ncol, K]
// CSR scratch
__device__ int g_deg[NN];
__device__ int g_off[NN + 1];
__device__ int g_fill[NN];
__device__ unsigned g_edge[EE];
__device__ int g_part[128];
__device__ int g_start[GG + 1];

// ---------------- helpers ----------------
__device__ __forceinline__ float tf32r(float x) {
    float y;
    asm("cvt.rna.tf32.f32 %0, %1;" : "=f"(y) : "f"(x));
    return y;
}
__device__ __forceinline__ uint32_t smem_u32(const void* p) {
    uint32_t a;
    asm("{ .reg .u64 t; cvta.to.shared.u64 t, %1; cvt.u32.u64 %0, t; }"
        : "=r"(a) : "l"(p));
    return a;
}
#define LDSM4(r, addr) \
    asm volatile("ldmatrix.sync.aligned.m8n8.x4.shared.b16 {%0,%1,%2,%3}, [%4];" \
                 : "=r"((r)[0]), "=r"((r)[1]), "=r"((r)[2]), "=r"((r)[3]) \
                 : "r"(addr))
#define MMA_TF32(d, a, b0, b1) \
    asm volatile("mma.sync.aligned.m16n8k8.row.col.f32.tf32.tf32.f32 " \
                 "{%0,%1,%2,%3}, {%4,%5,%6,%7}, {%8,%9}, {%0,%1,%2,%3};" \
                 : "+f"((d)[0]), "+f"((d)[1]), "+f"((d)[2]), "+f"((d)[3]) \
                 : "r"((a)[0]), "r"((a)[1]), "r"((a)[2]), "r"((a)[3]), \
                   "r"(b0), "r"(b1))

// ======== tf32 mma GEMM: C[M,Ncol] = act(A[M,K] @ Bt[Ncol,K]^T + bias)
// Bt is K-major [Ncol,K] (tf32-rounded). BM=128 BN=128 BK=32, 256 thr,
// warps 4(M) x 2(N), warp tile 32x64, mma m16n8k8 via ldmatrix.x4.
// 2-stage cp.async double buffer in dynamic smem (72 KB).
#define ALD2 36                    // padded floats per smem row: 144B stride,
                                   // +16B/row mod 128 -> conflict-free LDSM
#define STG2 (128 * ALD2)          // floats per stage per matrix (4608)
#define MG_SMEM (4 * STG2 * 4)     // bytes: 2 matrices x 2 stages = 73728

template <bool RELU, bool ROUND_OUT>
__global__ void __launch_bounds__(256)
mgemm_k(const float* __restrict__ A, const float* __restrict__ Bt,
        const float* __restrict__ bias, float* __restrict__ C,
        int M, int K, int Ncol) {
    extern __shared__ float smem_dyn[];
    float* sA = smem_dyn;              // [2][STG2]
    float* sB = smem_dyn + 2 * STG2;   // [2][STG2]

    const int tid = threadIdx.x;
    const int warp = tid >> 5;
    const int lane = tid & 31;
    const int wm = warp & 3;       // 4 warp rows (32 each)
    const int wn = warp >> 2;      // 2 warp cols (64 each)
    const int bm = blockIdx.y * 128;
    const int bn = blockIdx.x * 128;

    const uint32_t sA_u = smem_u32(sA);
    const uint32_t sB_u = smem_u32(sB);

    // per-lane LDSM byte offsets within a stage
    uint32_t aoff[2], boff[4];
#pragma unroll
    for (int mi = 0; mi < 2; mi++) {
        int row = wm * 32 + mi * 16 + (lane & 15);
        int col = (lane >> 4) * 4;
        aoff[mi] = (uint32_t)((row * ALD2 + col) * 4);
    }
#pragma unroll
    for (int pj = 0; pj < 4; pj++) {
        int nrow = wn * 64 + pj * 16 + (lane & 7) + ((lane >> 4) << 3);
        int col  = ((lane >> 3) & 1) * 4;
        boff[pj] = (uint32_t)((nrow * ALD2 + col) * 4);
    }

    float acc[2][8][4];
#pragma unroll
    for (int i = 0; i < 2; i++)
#pragma unroll
        for (int j = 0; j < 8; j++)
#pragma unroll
            for (int e = 0; e < 4; e++) acc[i][j][e] = 0.f;

    const int KT = (K + 31) / 32;

    auto load_tiles = [&](int s, int k0) {
#pragma unroll
        for (int i = 0; i < 4; i++) {
            int t = tid + i * 256;              // 1024 float4 tasks per matrix
            int row = t >> 3, q = t & 7;        // 8 float4 per 32-float row
            int gk = k0 + q * 4;
            // A
            {
                int gm = bm + row; if (gm >= M) gm = M - 1;
                float* dst = &sA[s * STG2 + row * ALD2 + q * 4];
                if (gk < K)
                    __pipeline_memcpy_async(dst, &A[(size_t)gm * K + gk], 16);
                else { dst[0] = 0.f; dst[1] = 0.f; dst[2] = 0.f; dst[3] = 0.f; }
            }
            // B (rows are N)
            {
                int gn = bn + row; if (gn >= Ncol) gn = Ncol - 1;
                float* dst = &sB[s * STG2 + row * ALD2 + q * 4];
                if (gk < K)
                    __pipeline_memcpy_async(dst, &Bt[(size_t)gn * K + gk], 16);
                else { dst[0] = 0.f; dst[1] = 0.f; dst[2] = 0.f; dst[3] = 0.f; }
            }
        }
    };

    load_tiles(0, 0);
    __pipeline_commit();

    for (int kt = 0; kt < KT; kt++) {
        int s = kt & 1;
        bool has_next = (kt + 1 < KT);
        if (has_next) { load_tiles(s ^ 1, (kt + 1) * 32); __pipeline_commit(); }
        __pipeline_wait_prior(has_next ? 1 : 0);
        __syncthreads();

        uint32_t baseA = sA_u + s * (STG2 * 4);
        uint32_t baseB = sB_u + s * (STG2 * 4);
#pragma unroll
        for (int kk8 = 0; kk8 < 4; kk8++) {
            uint32_t a[2][4], b[4][4];
#pragma unroll
            for (int mi = 0; mi < 2; mi++)
                LDSM4(a[mi], baseA + aoff[mi] + kk8 * 32);
#pragma unroll
            for (int pj = 0; pj < 4; pj++)
                LDSM4(b[pj], baseB + boff[pj] + kk8 * 32);
#pragma unroll
            for (int mi = 0; mi < 2; mi++)
#pragma unroll
                for (int pj = 0; pj < 4; pj++) {
                    MMA_TF32(acc[mi][2 * pj],     a[mi], b[pj][0], b[pj][1]);
                    MMA_TF32(acc[mi][2 * pj + 1], a[mi], b[pj][2], b[pj][3]);
                }
        }
        __syncthreads();
    }

    // ---- direct register epilogue (known m16n8 C layout) ----
    const int qr = lane >> 2;          // row within 8
    const int qc = 2 * (lane & 3);     // col pair base
#pragma unroll
    for (int mi = 0; mi < 2; mi++) {
        int gm0 = bm + wm * 32 + mi * 16 + qr;
        int gm1 = gm0 + 8;
#pragma unroll
        for (int nj = 0; nj < 8; nj++) {
            int gn = bn + wn * 64 + nj * 8 + qc;
            if (gn >= Ncol) continue;
            float2 bb = *(const float2*)&bias[gn];
            float* d = acc[mi][nj];
            if (gm0 < M) {
                float v0 = d[0] + bb.x, v1 = d[1] + bb.y;
                if (RELU) { v0 = fmaxf(v0, 0.f); v1 = fmaxf(v1, 0.f); }
                if (ROUND_OUT) { v0 = tf32r(v0); v1 = tf32r(v1); }
                *(float2*)&C[(size_t)gm0 * Ncol + gn] = make_float2(v0, v1);
            }
            if (gm1 < M) {
                float v2 = d[2] + bb.x, v3 = d[3] + bb.y;
                if (RELU) { v2 = fmaxf(v2, 0.f); v3 = fmaxf(v3, 0.f); }
                if (ROUND_OUT) { v2 = tf32r(v2); v3 = tf32r(v3); }
                *(float2*)&C[(size_t)gm1 * Ncol + gn] = make_float2(v2, v3);
            }
        }
    }
}

// ---------------- weight transpose+round: [K,Ncol] -> tf32 K-major [Ncol,K] --
__global__ void wt_k(const float* __restrict__ src, int K, int Ncol) {
    __shared__ float t[32][33];
    int bx = blockIdx.x * 32, by = blockIdx.y * 32;
    int x = bx + threadIdx.x;     // n
#pragma unroll
    for (int j = 0; j < 32; j += 8) {
        int y = by + threadIdx.y + j;   // k
        if (x < Ncol && y < K) t[threadIdx.y + j][threadIdx.x] = src[(size_t)y * Ncol + x];
    }
    __syncthreads();
    int xk = by + threadIdx.x;    // k
#pragma unroll
    for (int j = 0; j < 32; j += 8) {
        int yn = bx + threadIdx.y + j;  // n
        if (xk < K && yn < Ncol)
            g_wbuf[(size_t)yn * K + xk] = tf32r(t[threadIdx.x][threadIdx.y + j]);
    }
}

// ---------------- node embed ----------------
__global__ void embed_k(const int* __restrict__ x,
                        const float* __restrict__ e1,
                        const float* __restrict__ e2) {
    long long i = (long long)blockIdx.x * blockDim.x + threadIdx.x;
    if (i >= (long long)NN * EMB) return;
    int r = (int)(i / EMB);
    int f = (int)(i - (long long)r * EMB);
    g_h[i] = e1[x[2 * r] * EMB + f] + e2[x[2 * r + 1] * EMB + f];
}

// ---------------- CSR build (once per call) ----------------
__global__ void deg_zero_k() {
    int i = blockIdx.x * blockDim.x + threadIdx.x;
    if (i < NN) g_deg[i] = 0;
}
__global__ void deg_count_k(const int* __restrict__ ei) {
    int e = blockIdx.x * blockDim.x + threadIdx.x;
    if (e < EE) atomicAdd(&g_deg[ei[EE + e]], 1);
}
__global__ void scan1_k() {
    __shared__ int ssum[256];
    int tid = threadIdx.x;
    int base = blockIdx.x * 1024;
    int v[4]; int tot = 0;
#pragma unroll
    for (int i = 0; i < 4; i++) {
        int idx = base + tid * 4 + i;
        v[i] = (idx < NN) ? g_deg[idx] : 0;
        tot += v[i];
    }
    ssum[tid] = tot;
    __syncthreads();
    for (int off = 1; off < 256; off <<= 1) {
        int t = (tid >= off) ? ssum[tid - off] : 0;
        __syncthreads();
        ssum[tid] += t;
        __syncthreads();
    }
    int run = ssum[tid] - tot;
#pragma unroll
    for (int i = 0; i < 4; i++) {
        int idx = base + tid * 4 + i;
        if (idx < NN) g_off[idx] = run;
        run += v[i];
    }
    if (tid == 255) g_part[blockIdx.x] = ssum[255];
}
__global__ void scan2_k(int nb) {
    if (threadIdx.x == 0) {
        int run = 0;
        for (int b = 0; b < nb; b++) { int t = g_part[b]; g_part[b] = run; run += t; }
    }
}
__global__ void scan3_k() {
    int i = blockIdx.x * blockDim.x + threadIdx.x;
    if (i < NN) {
        int o = g_off[i] + g_part[i >> 10];
        g_off[i] = o;
        g_fill[i] = o;
    }
    if (i == 0) g_off[NN] = EE;
}
__global__ void fill_k(const int* __restrict__ ei, const int* __restrict__ ea) {
    int e = blockIdx.x * blockDim.x + threadIdx.x;
    if (e >= EE) return;
    int s = ei[e];
    int d = ei[EE + e];
    unsigned combo = (unsigned)(ea[2 * e] * 3 + ea[2 * e + 1]);
    int pos = atomicAdd(&g_fill[d], 1);
    g_edge[pos] = (unsigned)s | (combo << 17);
}

// ---------------- per-layer combo table ----------------
__global__ void ctab_k(const float* __restrict__ ee1l, const float* __restrict__ ee2l) {
    int i = blockIdx.x * blockDim.x + threadIdx.x;
    if (i >= 18 * EMB) return;
    int combo = i / EMB, f = i - combo * EMB;
    g_ctab[i] = ee1l[(combo / 3) * EMB + f] + ee2l[(combo % 3) * EMB + f];
}

// ---------------- gather: warp/node, BN+ReLU fused, tf32-rounded out --------
// 512 threads = 16 nodes per block (halves ctab reload traffic, averages tail)
template <bool BN>
__global__ void __launch_bounds__(512)
gather_k() {
    __shared__ float4 sctab[18 * EMB / 4];
    __shared__ float4 ssc[EMB / 4 + 1];
    __shared__ float4 ssh[EMB / 4 + 1];
    int tid = threadIdx.x;
    const float4* gt = (const float4*)g_ctab;
    for (int i = tid; i < 18 * EMB / 4; i += 512) sctab[i] = gt[i];
    if (BN) {
        const float4* sc = (const float4*)g_bnscale;
        const float4* sh = (const float4*)g_bnshift;
        for (int i = tid; i < EMB / 4; i += 512) { ssc[i] = sc[i]; ssh[i] = sh[i]; }
    }
    __syncthreads();
    int node = blockIdx.x * 16 + (tid >> 5);
    if (node >= NN) return;
    int lane = tid & 31;
    int i0 = lane, i1 = lane + 32, i2 = lane + 64;
    float4 sc0, sc1, sc2, sh0, sh1, sh2;
    if (BN) {
        sc0 = ssc[i0]; sh0 = ssh[i0];
        sc1 = ssc[i1]; sh1 = ssh[i1];
        if (lane < 11) { sc2 = ssc[i2]; sh2 = ssh[i2]; }
    }
    auto norm = [&](float4 h, const float4& sc, const float4& sh) -> float4 {
        if (!BN) return h;
        return make_float4(fmaxf(fmaf(h.x, sc.x, sh.x), 0.f),
                           fmaxf(fmaf(h.y, sc.y, sh.y), 0.f),
                           fmaxf(fmaf(h.z, sc.z, sh.z), 0.f),
                           fmaxf(fmaf(h.w, sc.w, sh.w), 0.f));
    };
    float4 a0, a1, a2;
    {
        const float4* hn = (const float4*)(g_h + (size_t)node * EMB);
        const float4* self = &sctab[12 * 75];
        float4 h0 = norm(hn[i0], sc0, sh0), c0 = self[i0];
        float4 h1 = norm(hn[i1], sc1, sh1), c1 = self[i1];
        a0 = make_float4(h0.x + c0.x, h0.y + c0.y, h0.z + c0.z, h0.w + c0.w);
        a1 = make_float4(h1.x + c1.x, h1.y + c1.y, h1.z + c1.z, h1.w + c1.w);
        a2 = make_float4(0.f, 0.f, 0.f, 0.f);
        if (lane < 11) {
            float4 h2 = norm(hn[i2], sc2, sh2), c2 = self[i2];
            a2 = make_float4(h2.x + c2.x, h2.y + c2.y, h2.z + c2.z, h2.w + c2.w);
        }
    }
    int s = g_off[node], e = g_off[node + 1];
    int p = s;
    for (; p + 1 < e; p += 2) {
        unsigned pka = g_edge[p], pkb = g_edge[p + 1];
        const float4* ha = (const float4*)(g_h + (size_t)(pka & SRCMASK) * EMB);
        const float4* hb = (const float4*)(g_h + (size_t)(pkb & SRCMASK) * EMB);
        const float4* ca = &sctab[(pka >> 17) * 75];
        const float4* cb = &sctab[(pkb >> 17) * 75];
        float4 ha0 = ha[i0], hb0 = hb[i0];
        float4 ha1 = ha[i1], hb1 = hb[i1];
        float4 ha2, hb2;
        if (lane < 11) { ha2 = ha[i2]; hb2 = hb[i2]; }
        ha0 = norm(ha0, sc0, sh0); hb0 = norm(hb0, sc0, sh0);
        ha1 = norm(ha1, sc1, sh1); hb1 = norm(hb1, sc1, sh1);
        float4 c;
        c = ca[i0]; a0.x += ha0.x + c.x; a0.y += ha0.y + c.y; a0.z += ha0.z + c.z; a0.w += ha0.w + c.w;
        c = cb[i0]; a0.x += hb0.x + c.x; a0.y += hb0.y + c.y; a0.z += hb0.z + c.z; a0.w += hb0.w + c.w;
        c = ca[i1]; a1.x += ha1.x + c.x; a1.y += ha1.y + c.y; a1.z += ha1.z + c.z; a1.w += ha1.w + c.w;
        c = cb[i1]; a1.x += hb1.x + c.x; a1.y += hb1.y + c.y; a1.z += hb1.z + c.z; a1.w += hb1.w + c.w;
        if (lane < 11) {
            ha2 = norm(ha2, sc2, sh2); hb2 = norm(hb2, sc2, sh2);
            c = ca[i2]; a2.x += ha2.x + c.x; a2.y += ha2.y + c.y; a2.z += ha2.z + c.z; a2.w += ha2.w + c.w;
            c = cb[i2]; a2.x += hb2.x + c.x; a2.y += hb2.y + c.y; a2.z += hb2.z + c.z; a2.w += hb2.w + c.w;
        }
    }
    for (; p < e; p++) {
        unsigned pk = g_edge[p];
        const float4* hs = (const float4*)(g_h + (size_t)(pk & SRCMASK) * EMB);
        const float4* ct = &sctab[(pk >> 17) * 75];
        float4 h0 = norm(hs[i0], sc0, sh0), c0 = ct[i0];
        a0.x += h0.x + c0.x; a0.y += h0.y + c0.y; a0.z += h0.z + c0.z; a0.w += h0.w + c0.w;
        float4 h1 = norm(hs[i1], sc1, sh1), c1 = ct[i1];
        a1.x += h1.x + c1.x; a1.y += h1.y + c1.y; a1.z += h1.z + c1.z; a1.w += h1.w + c1.w;
        if (lane < 11) {
            float4 h2 = norm(hs[i2], sc2, sh2), c2 = ct[i2];
            a2.x += h2.x + c2.x; a2.y += h2.y + c2.y; a2.z += h2.z + c2.z; a2.w += h2.w + c2.w;
        }
    }
    auto rnd4 = [](float4 v) {
        return make_float4(tf32r(v.x), tf32r(v.y), tf32r(v.z), tf32r(v.w));
    };
    float4* ag = (float4*)(g_agg + (size_t)node * EMB);
    ag[i0] = rnd4(a0);
    ag[i1] = rnd4(a1);
    if (lane < 11) ag[i2] = rnd4(a2);
}

// ---------------- BatchNorm ----------------
__global__ void bn_zero_k() {
    int i = threadIdx.x;
    if (i < EMB) { g_bnsum[i] = 0.f; g_bnsq[i] = 0.f; }
}
__global__ void bn_stats_k() {
    int f = threadIdx.x;
    if (f >= EMB) return;
    long long r0 = (long long)blockIdx.x * 512;
    long long r1 = r0 + 512; if (r1 > NN) r1 = NN;
    float s = 0.f, q = 0.f;
    for (long long r = r0; r < r1; r++) {
        float v = g_h[r * EMB + f];
        s += v; q += v * v;
    }
    atomicAdd(&g_bnsum[f], s);
    atomicAdd(&g_bnsq[f], q);
}
__global__ void bnfin_k(const float* __restrict__ gamma,
                        const float* __restrict__ beta) {
    int f = threadIdx.x;
    if (f >= EMB) return;
    float m   = g_bnsum[f] * (1.f / NN);
    float var = g_bnsq[f] * (1.f / NN) - m * m;
    float sc  = rsqrtf(var + EPSV) * gamma[f];
    g_bnscale[f] = sc;
    g_bnshift[f] = beta[f] - m * sc;
}
__global__ void bn_apply_k() {
    long long i = (long long)blockIdx.x * blockDim.x + threadIdx.x;
    if (i >= (long long)NN * EMB) return;
    int f = (int)(i % EMB);
    g_h[i] = tf32r(fmaxf(fmaf(g_h[i], g_bnscale[f], g_bnshift[f]), 0.f));
}

// ---------------- pooling ----------------
__global__ void start_init_k() {
    int g = blockIdx.x * blockDim.x + threadIdx.x;
    if (g <= GG) g_start[g] = NN;
}
__global__ void bounds_k(const int* __restrict__ batch) {
    int r = blockIdx.x * blockDim.x + threadIdx.x;
    if (r >= NN) return;
    int b = batch[r];
    int pb = (r == 0) ? -1 : batch[r - 1];
    for (int g = pb + 1; g <= b; g++) g_start[g] = r;
}
__global__ void __launch_bounds__(256)
pool_g_k(float* __restrict__ out) {
    int g = blockIdx.x, f = threadIdx.x;
    int s = g_start[g], e = g_start[g + 1];
    float acc = 0.f;
    for (int r = s; r < e; r++) acc += g_hf[(size_t)r * FEATD + f];
    float c = fmaxf((float)(e - s), 1.f);
    float v = acc / c;
    out[(size_t)g * FEATD + f] = v;
    g_pool[(size_t)g * FEATD + f] = v;
}

// head
__global__ void __launch_bounds__(128)
pred_k(const float* __restrict__ pw1, const float* __restrict__ pb1,
       const float* __restrict__ pw2, const float* __restrict__ pb2,
       float* __restrict__ out) {
    __shared__ float sp[FEATD];
    __shared__ float sh[128];
    int g = blockIdx.x, t = threadIdx.x;
    sp[t]       = g_pool[(size_t)g * FEATD + t];
    sp[t + 128] = g_pool[(size_t)g * FEATD + t + 128];
    __syncthreads();
    float acc = pb1[t];
    for (int k = 0; k < FEATD; k++) acc = fmaf(sp[k], pw1[k * 128 + t], acc);
    sh[t] = fmaxf(acc, 0.f);
    __syncthreads();
    if (t < 2) {
        float a = pb2[t];
        for (int k = 0; k < 128; k++) a = fmaf(sh[k], pw2[k * 2 + t], a);
        out[(size_t)GG * FEATD + g * 2 + t] = a;
    }
}

// ---------------- launch ----------------
extern "C" void kernel_launch(void* const* d_in, const int* in_sizes, int n_in,
                              void* d_out, int out_size) {
    const int*   x     = (const int*)d_in[0];
    const int*   ei    = (const int*)d_in[1];
    const int*   ea    = (const int*)d_in[2];
    const int*   batch = (const int*)d_in[3];
    const float* xemb1 = (const float*)d_in[4];
    const float* xemb2 = (const float*)d_in[5];
    const float* ee1   = (const float*)d_in[6];
    const float* ee2   = (const float*)d_in[7];
    const float* w1    = (const float*)d_in[8];
    const float* b1    = (const float*)d_in[9];
    const float* w2    = (const float*)d_in[10];
    const float* b2    = (const float*)d_in[11];
    const float* gamma = (const float*)d_in[12];
    const float* beta  = (const float*)d_in[13];
    const float* fw    = (const float*)d_in[14];
    const float* fb    = (const float*)d_in[15];
    const float* pw1   = (const float*)d_in[16];
    const float* pb1   = (const float*)d_in[17];
    const float* pw2   = (const float*)d_in[18];
    const float* pb2   = (const float*)d_in[19];
    float* out = (float*)d_out;

    float *p_h, *p_agg, *p_hidden, *p_hf, *p_wbuf;
    cudaGetSymbolAddress((void**)&p_h, g_h);
    cudaGetSymbolAddress((void**)&p_agg, g_agg);
    cudaGetSymbolAddress((void**)&p_hidden, g_hidden);
    cudaGetSymbolAddress((void**)&p_hf, g_hf);
    cudaGetSymbolAddress((void**)&p_wbuf, g_wbuf);

    // allow 72KB dynamic smem for the GEMM (non-stream call; capture-safe)
    cudaFuncSetAttribute(mgemm_k<true, true>,
                         cudaFuncAttributeMaxDynamicSharedMemorySize, MG_SMEM);
    cudaFuncSetAttribute(mgemm_k<false, false>,
                         cudaFuncAttributeMaxDynamicSharedMemorySize, MG_SMEM);

    const long long nelem = (long long)NN * EMB;
    const int T = 256;
    const int gNE = (int)((nelem + T - 1) / T);
    const int MB = (NN + 127) / 128;
    const int NB_SCAN = (NN + 1023) / 1024;
    dim3 tb(32, 8);

    embed_k<<<gNE, T>>>(x, xemb1, xemb2);

    deg_zero_k<<<(NN + T - 1) / T, T>>>();
    deg_count_k<<<(EE + T - 1) / T, T>>>(ei);
    scan1_k<<<NB_SCAN, 256>>>();
    scan2_k<<<1, 32>>>(NB_SCAN);
    scan3_k<<<(NN + T - 1) / T, T>>>();
    fill_k<<<(EE + T - 1) / T, T>>>(ei, ea);

    for (int l = 0; l < LL; l++) {
        const float* ee1l = ee1 + (size_t)l * 6 * EMB;
        const float* ee2l = ee2 + (size_t)l * 3 * EMB;
        ctab_k<<<(18 * EMB + T - 1) / T, T>>>(ee1l, ee2l);
        if (l == 0) gather_k<false><<<(NN + 15) / 16, 512>>>();
        else        gather_k<true><<<(NN + 15) / 16, 512>>>();

        // GEMM1: [NN,300] @ [300,600], relu, tf32-rounded output
        wt_k<<<dim3((H2 + 31) / 32, (EMB + 31) / 32), tb>>>(w1 + (size_t)l * EMB * H2, EMB, H2);
        mgemm_k<true, true><<<dim3((H2 + 127) / 128, MB), 256, MG_SMEM>>>(
            p_agg, p_wbuf, b1 + (size_t)l * H2, p_hidden, NN, EMB, H2);
        // GEMM2: [NN,600] @ [600,300]
        wt_k<<<dim3((EMB + 31) / 32, (H2 + 31) / 32), tb>>>(w2 + (size_t)l * H2 * EMB, H2, EMB);
        mgemm_k<false, false><<<dim3((EMB + 127) / 128, MB), 256, MG_SMEM>>>(
            p_hidden, p_wbuf, b2 + (size_t)l * EMB, p_h, NN, H2, EMB);

        bn_zero_k<<<1, 320>>>();
        bn_stats_k<<<(NN + 511) / 512, 320>>>();
        bnfin_k<<<1, 320>>>(gamma + (size_t)l * EMB, beta + (size_t)l * EMB);
    }

    bn_apply_k<<<gNE, T>>>();
    wt_k<<<dim3((FEATD + 31) / 32, (EMB + 31) / 32), tb>>>(fw, EMB, FEATD);
    mgemm_k<false, false><<<dim3((FEATD + 127) / 128, MB), 256, MG_SMEM>>>(
        p_h, p_wbuf, fb, p_hf, NN, EMB, FEATD);

    start_init_k<<<(GG + 1 + T - 1) / T, T>>>();
    bounds_k<<<(NN + T - 1) / T, T>>>(batch);
    pool_g_k<<<GG, FEATD>>>(out);
    pred_k<<<GG, 128>>>(pw1, pb1, pw2, pb2, out);
}

// round 12
// speedup vs baseline: 1.1802x; 1.1802x over previous
#include <cuda_runtime.h>
#include <cuda_bf16.h>
#include <cuda_pipeline_primitives.h>
#include <cstdio>
#include <cstdint>

#define NN 100000
#define EE 500000
#define GG 2000
#define LL 5
#define EMB 300
#define H2  600
#define FEATD 256
#define EPSV 1e-5f
#define SRCMASK 0x1FFFF

// ---------------- scratch (device globals; no allocs allowed) ----------------
__device__ float g_h[(size_t)NN * EMB];
__device__ float g_agg[(size_t)NN * EMB];
__device__ float g_hidden[(size_t)NN * H2];
__device__ float g_hf[(size_t)NN * FEATD];
__device__ float g_bnsum[EMB];
__device__ float g_bnsq[EMB];
__device__ float g_bnscale[EMB];
__device__ float g_bnshift[EMB];
__device__ float g_pool[(size_t)GG * FEATD];
__device__ float g_ctab[18 * EMB];
__device__ float g_wbuf[EMB * H2];     // K-major tf32-rounded weights [Ncol, K]
// CSR scratch
__device__ int g_deg[NN];
__device__ int g_off[NN + 1];
__device__ int g_fill[NN];
__device__ unsigned g_edge[EE];
__device__ int g_part[128];
__device__ int g_start[GG + 1];

// ---------------- helpers ----------------
__device__ __forceinline__ float tf32r(float x) {
    float y;
    asm("cvt.rna.tf32.f32 %0, %1;" : "=f"(y) : "f"(x));
    return y;
}
__device__ __forceinline__ uint32_t smem_u32(const void* p) {
    uint32_t a;
    asm("{ .reg .u64 t; cvta.to.shared.u64 t, %1; cvt.u32.u64 %0, t; }"
        : "=r"(a) : "l"(p));
    return a;
}
#define LDSM4(r, addr) \
    asm volatile("ldmatrix.sync.aligned.m8n8.x4.shared.b16 {%0,%1,%2,%3}, [%4];" \
                 : "=r"((r)[0]), "=r"((r)[1]), "=r"((r)[2]), "=r"((r)[3]) \
                 : "r"(addr))
#define MMA_TF32(d, a, b0, b1) \
    asm volatile("mma.sync.aligned.m16n8k8.row.col.f32.tf32.tf32.f32 " \
                 "{%0,%1,%2,%3}, {%4,%5,%6,%7}, {%8,%9}, {%0,%1,%2,%3};" \
                 : "+f"((d)[0]), "+f"((d)[1]), "+f"((d)[2]), "+f"((d)[3]) \
                 : "r"((a)[0]), "r"((a)[1]), "r"((a)[2]), "r"((a)[3]), \
                   "r"(b0), "r"(b1))

// ======== hand-rolled tf32 mma GEMM: C[M,Ncol] = act(A[M,K] @ Bt[Ncol,K]^T + bias)
// Bt is K-major [Ncol,K] (tf32-rounded). BM=128 BN=128 BK=16, 256 thr,
// warps 4(M) x 2(N), warp tile 32x64, mma m16n8k8 via ldmatrix.x4.
// (round-10 winning config: static 40KB smem, 2-stage cp.async)
#define ALD 20                     // padded floats per smem row (conflict-free LDSM)
#define STG_FLT (128 * ALD)        // 2560 floats = 10240 B per tile stage

template <bool RELU, bool ROUND_OUT, bool STATS>
__global__ void __launch_bounds__(256)
mgemm_k(const float* __restrict__ A, const float* __restrict__ Bt,
        const float* __restrict__ bias, float* __restrict__ C,
        int M, int K, int Ncol) {
    __shared__ __align__(16) float sA[2 * STG_FLT];
    __shared__ __align__(16) float sB[2 * STG_FLT];

    const int tid = threadIdx.x;
    const int warp = tid >> 5;
    const int lane = tid & 31;
    const int wm = warp & 3;       // 4 warp rows (32 each)
    const int wn = warp >> 2;      // 2 warp cols (64 each)
    const int bm = blockIdx.y * 128;
    const int bn = blockIdx.x * 128;

    const uint32_t sA_u = smem_u32(sA);
    const uint32_t sB_u = smem_u32(sB);

    // per-lane LDSM byte offsets within a stage
    uint32_t aoff[2], boff[4];
#pragma unroll
    for (int mi = 0; mi < 2; mi++) {
        int row = wm * 32 + mi * 16 + (lane & 15);
        int col = (lane >> 4) * 4;
        aoff[mi] = (uint32_t)((row * ALD + col) * 4);
    }
#pragma unroll
    for (int pj = 0; pj < 4; pj++) {
        int nrow = wn * 64 + pj * 16 + (lane & 7) + ((lane >> 4) << 3);
        int col  = ((lane >> 3) & 1) * 4;
        boff[pj] = (uint32_t)((nrow * ALD + col) * 4);
    }

    float acc[2][8][4];
#pragma unroll
    for (int i = 0; i < 2; i++)
#pragma unroll
        for (int j = 0; j < 8; j++)
#pragma unroll
            for (int e = 0; e < 4; e++) acc[i][j][e] = 0.f;

    const int KT = (K + 15) / 16;

    auto load_tiles = [&](int s, int k0) {
#pragma unroll
        for (int i = 0; i < 2; i++) {
            int t = tid + i * 256;              // 512 float4 tasks per tile
            int row = t >> 2, q = t & 3;
            int gk = k0 + q * 4;
            // A
            {
                int gm = bm + row; if (gm >= M) gm = M - 1;
                float* dst = &sA[s * STG_FLT + row * ALD + q * 4];
                if (gk < K)
                    __pipeline_memcpy_async(dst, &A[(size_t)gm * K + gk], 16);
                else { dst[0] = 0.f; dst[1] = 0.f; dst[2] = 0.f; dst[3] = 0.f; }
            }
            // B (rows are N)
            {
                int gn = bn + row; if (gn >= Ncol) gn = Ncol - 1;
                float* dst = &sB[s * STG_FLT + row * ALD + q * 4];
                if (gk < K)
                    __pipeline_memcpy_async(dst, &Bt[(size_t)gn * K + gk], 16);
                else { dst[0] = 0.f; dst[1] = 0.f; dst[2] = 0.f; dst[3] = 0.f; }
            }
        }
    };

    load_tiles(0, 0);
    __pipeline_commit();

    for (int kt = 0; kt < KT; kt++) {
        int s = kt & 1;
        bool has_next = (kt + 1 < KT);
        if (has_next) { load_tiles(s ^ 1, (kt + 1) * 16); __pipeline_commit(); }
        __pipeline_wait_prior(has_next ? 1 : 0);
        __syncthreads();

        uint32_t baseA = sA_u + s * (STG_FLT * 4);
        uint32_t baseB = sB_u + s * (STG_FLT * 4);
#pragma unroll
        for (int kk8 = 0; kk8 < 2; kk8++) {
            uint32_t a[2][4], b[4][4];
#pragma unroll
            for (int mi = 0; mi < 2; mi++)
                LDSM4(a[mi], baseA + aoff[mi] + kk8 * 32);
#pragma unroll
            for (int pj = 0; pj < 4; pj++)
                LDSM4(b[pj], baseB + boff[pj] + kk8 * 32);
#pragma unroll
            for (int mi = 0; mi < 2; mi++)
#pragma unroll
                for (int pj = 0; pj < 4; pj++) {
                    MMA_TF32(acc[mi][2 * pj],     a[mi], b[pj][0], b[pj][1]);
                    MMA_TF32(acc[mi][2 * pj + 1], a[mi], b[pj][2], b[pj][3]);
                }
        }
        __syncthreads();
    }

    // ---- direct register epilogue (known m16n8 C layout), optional BN stats --
    const int qr = lane >> 2;          // row within 8
    const int qc = 2 * (lane & 3);     // col pair base
#pragma unroll
    for (int nj = 0; nj < 8; nj++) {
        int gn = bn + wn * 64 + nj * 8 + qc;
        float s0 = 0.f, s1 = 0.f, q0 = 0.f, q1 = 0.f;
        if (gn < Ncol) {
            float2 bb = *(const float2*)&bias[gn];
#pragma unroll
            for (int mi = 0; mi < 2; mi++) {
                int gm0 = bm + wm * 32 + mi * 16 + qr;
                int gm1 = gm0 + 8;
                float* d = acc[mi][nj];
                if (gm0 < M) {
                    float v0 = d[0] + bb.x, v1 = d[1] + bb.y;
                    if (RELU) { v0 = fmaxf(v0, 0.f); v1 = fmaxf(v1, 0.f); }
                    if (STATS) { s0 += v0; s1 += v1; q0 += v0 * v0; q1 += v1 * v1; }
                    if (ROUND_OUT) { v0 = tf32r(v0); v1 = tf32r(v1); }
                    *(float2*)&C[(size_t)gm0 * Ncol + gn] = make_float2(v0, v1);
                }
                if (gm1 < M) {
                    float v2 = d[2] + bb.x, v3 = d[3] + bb.y;
                    if (RELU) { v2 = fmaxf(v2, 0.f); v3 = fmaxf(v3, 0.f); }
                    if (STATS) { s0 += v2; s1 += v3; q0 += v2 * v2; q1 += v3 * v3; }
                    if (ROUND_OUT) { v2 = tf32r(v2); v3 = tf32r(v3); }
                    *(float2*)&C[(size_t)gm1 * Ncol + gn] = make_float2(v2, v3);
                }
            }
        }
        if (STATS) {
            // reduce across lanes sharing the same column (lane & 3 groups)
#pragma unroll
            for (int off = 4; off < 32; off <<= 1) {
                s0 += __shfl_xor_sync(0xFFFFFFFF, s0, off);
                s1 += __shfl_xor_sync(0xFFFFFFFF, s1, off);
                q0 += __shfl_xor_sync(0xFFFFFFFF, q0, off);
                q1 += __shfl_xor_sync(0xFFFFFFFF, q1, off);
            }
            if (lane < 4) {
                int cgn = bn + wn * 64 + nj * 8 + 2 * lane;
                if (cgn < Ncol) {
                    atomicAdd(&g_bnsum[cgn],     s0);
                    atomicAdd(&g_bnsum[cgn + 1], s1);
                    atomicAdd(&g_bnsq[cgn],      q0);
                    atomicAdd(&g_bnsq[cgn + 1],  q1);
                }
            }
        }
    }
}

// ---------------- weight transpose+round: [K,Ncol] -> tf32 K-major [Ncol,K] --
__global__ void wt_k(const float* __restrict__ src, int K, int Ncol) {
    __shared__ float t[32][33];
    int bx = blockIdx.x * 32, by = blockIdx.y * 32;
    int x = bx + threadIdx.x;     // n
#pragma unroll
    for (int j = 0; j < 32; j += 8) {
        int y = by + threadIdx.y + j;   // k
        if (x < Ncol && y < K) t[threadIdx.y + j][threadIdx.x] = src[(size_t)y * Ncol + x];
    }
    __syncthreads();
    int xk = by + threadIdx.x;    // k
#pragma unroll
    for (int j = 0; j < 32; j += 8) {
        int yn = bx + threadIdx.y + j;  // n
        if (xk < K && yn < Ncol)
            g_wbuf[(size_t)yn * K + xk] = tf32r(t[threadIdx.x][threadIdx.y + j]);
    }
}

// ---------------- node embed ----------------
__global__ void embed_k(const int* __restrict__ x,
                        const float* __restrict__ e1,
                        const float* __restrict__ e2) {
    long long i = (long long)blockIdx.x * blockDim.x + threadIdx.x;
    if (i >= (long long)NN * EMB) return;
    int r = (int)(i / EMB);
    int f = (int)(i - (long long)r * EMB);
    g_h[i] = e1[x[2 * r] * EMB + f] + e2[x[2 * r + 1] * EMB + f];
}

// ---------------- CSR build (once per call) ----------------
__global__ void deg_zero_k() {
    int i = blockIdx.x * blockDim.x + threadIdx.x;
    if (i < NN) g_deg[i] = 0;
}
__global__ void deg_count_k(const int* __restrict__ ei) {
    int e = blockIdx.x * blockDim.x + threadIdx.x;
    if (e < EE) atomicAdd(&g_deg[ei[EE + e]], 1);
}
__global__ void scan1_k() {
    __shared__ int ssum[256];
    int tid = threadIdx.x;
    int base = blockIdx.x * 1024;
    int v[4]; int tot = 0;
#pragma unroll
    for (int i = 0; i < 4; i++) {
        int idx = base + tid * 4 + i;
        v[i] = (idx < NN) ? g_deg[idx] : 0;
        tot += v[i];
    }
    ssum[tid] = tot;
    __syncthreads();
    for (int off = 1; off < 256; off <<= 1) {
        int t = (tid >= off) ? ssum[tid - off] : 0;
        __syncthreads();
        ssum[tid] += t;
        __syncthreads();
    }
    int run = ssum[tid] - tot;
#pragma unroll
    for (int i = 0; i < 4; i++) {
        int idx = base + tid * 4 + i;
        if (idx < NN) g_off[idx] = run;
        run += v[i];
    }
    if (tid == 255) g_part[blockIdx.x] = ssum[255];
}
__global__ void scan2_k(int nb) {
    if (threadIdx.x == 0) {
        int run = 0;
        for (int b = 0; b < nb; b++) { int t = g_part[b]; g_part[b] = run; run += t; }
    }
}
__global__ void scan3_k() {
    int i = blockIdx.x * blockDim.x + threadIdx.x;
    if (i < NN) {
        int o = g_off[i] + g_part[i >> 10];
        g_off[i] = o;
        g_fill[i] = o;
    }
    if (i == 0) g_off[NN] = EE;
}
__global__ void fill_k(const int* __restrict__ ei, const int* __restrict__ ea) {
    int e = blockIdx.x * blockDim.x + threadIdx.x;
    if (e >= EE) return;
    int s = ei[e];
    int d = ei[EE + e];
    unsigned combo = (unsigned)(ea[2 * e] * 3 + ea[2 * e + 1]);
    int pos = atomicAdd(&g_fill[d], 1);
    g_edge[pos] = (unsigned)s | (combo << 17);
}

// ---------------- per-layer combo table ----------------
__global__ void ctab_k(const float* __restrict__ ee1l, const float* __restrict__ ee2l) {
    int i = blockIdx.x * blockDim.x + threadIdx.x;
    if (i >= 18 * EMB) return;
    int combo = i / EMB, f = i - combo * EMB;
    g_ctab[i] = ee1l[(combo / 3) * EMB + f] + ee2l[(combo % 3) * EMB + f];
}

// ---------------- gather: warp/node, BN+ReLU fused, tf32-rounded out --------
template <bool BN>
__global__ void __launch_bounds__(256)
gather_k() {
    __shared__ float4 sctab[18 * EMB / 4];
    __shared__ float4 ssc[EMB / 4 + 1];
    __shared__ float4 ssh[EMB / 4 + 1];
    int tid = threadIdx.x;
    const float4* gt = (const float4*)g_ctab;
    for (int i = tid; i < 18 * EMB / 4; i += 256) sctab[i] = gt[i];
    if (BN) {
        const float4* sc = (const float4*)g_bnscale;
        const float4* sh = (const float4*)g_bnshift;
        for (int i = tid; i < EMB / 4; i += 256) { ssc[i] = sc[i]; ssh[i] = sh[i]; }
    }
    __syncthreads();
    int node = blockIdx.x * 8 + (tid >> 5);
    if (node >= NN) return;
    int lane = tid & 31;
    int i0 = lane, i1 = lane + 32, i2 = lane + 64;
    float4 sc0, sc1, sc2, sh0, sh1, sh2;
    if (BN) {
        sc0 = ssc[i0]; sh0 = ssh[i0];
        sc1 = ssc[i1]; sh1 = ssh[i1];
        if (lane < 11) { sc2 = ssc[i2]; sh2 = ssh[i2]; }
    }
    auto norm = [&](float4 h, const float4& sc, const float4& sh) -> float4 {
        if (!BN) return h;
        return make_float4(fmaxf(fmaf(h.x, sc.x, sh.x), 0.f),
                           fmaxf(fmaf(h.y, sc.y, sh.y), 0.f),
                           fmaxf(fmaf(h.z, sc.z, sh.z), 0.f),
                           fmaxf(fmaf(h.w, sc.w, sh.w), 0.f));
    };
    float4 a0, a1, a2;
    {
        const float4* hn = (const float4*)(g_h + (size_t)node * EMB);
        const float4* self = &sctab[12 * 75];
        float4 h0 = norm(hn[i0], sc0, sh0), c0 = self[i0];
        float4 h1 = norm(hn[i1], sc1, sh1), c1 = self[i1];
        a0 = make_float4(h0.x + c0.x, h0.y + c0.y, h0.z + c0.z, h0.w + c0.w);
        a1 = make_float4(h1.x + c1.x, h1.y + c1.y, h1.z + c1.z, h1.w + c1.w);
        a2 = make_float4(0.f, 0.f, 0.f, 0.f);
        if (lane < 11) {
            float4 h2 = norm(hn[i2], sc2, sh2), c2 = self[i2];
            a2 = make_float4(h2.x + c2.x, h2.y + c2.y, h2.z + c2.z, h2.w + c2.w);
        }
    }
    int s = g_off[node], e = g_off[node + 1];
    int p = s;
    for (; p + 1 < e; p += 2) {
        unsigned pka = g_edge[p], pkb = g_edge[p + 1];
        const float4* ha = (const float4*)(g_h + (size_t)(pka & SRCMASK) * EMB);
        const float4* hb = (const float4*)(g_h + (size_t)(pkb & SRCMASK) * EMB);
        const float4* ca = &sctab[(pka >> 17) * 75];
        const float4* cb = &sctab[(pkb >> 17) * 75];
        float4 ha0 = ha[i0], hb0 = hb[i0];
        float4 ha1 = ha[i1], hb1 = hb[i1];
        float4 ha2, hb2;
        if (lane < 11) { ha2 = ha[i2]; hb2 = hb[i2]; }
        ha0 = norm(ha0, sc0, sh0); hb0 = norm(hb0, sc0, sh0);
        ha1 = norm(ha1, sc1, sh1); hb1 = norm(hb1, sc1, sh1);
        float4 c;
        c = ca[i0]; a0.x += ha0.x + c.x; a0.y += ha0.y + c.y; a0.z += ha0.z + c.z; a0.w += ha0.w + c.w;
        c = cb[i0]; a0.x += hb0.x + c.x; a0.y += hb0.y + c.y; a0.z += hb0.z + c.z; a0.w += hb0.w + c.w;
        c = ca[i1]; a1.x += ha1.x + c.x; a1.y += ha1.y + c.y; a1.z += ha1.z + c.z; a1.w += ha1.w + c.w;
        c = cb[i1]; a1.x += hb1.x + c.x; a1.y += hb1.y + c.y; a1.z += hb1.z + c.z; a1.w += hb1.w + c.w;
        if (lane < 11) {
            ha2 = norm(ha2, sc2, sh2); hb2 = norm(hb2, sc2, sh2);
            c = ca[i2]; a2.x += ha2.x + c.x; a2.y += ha2.y + c.y; a2.z += ha2.z + c.z; a2.w += ha2.w + c.w;
            c = cb[i2]; a2.x += hb2.x + c.x; a2.y += hb2.y + c.y; a2.z += hb2.z + c.z; a2.w += hb2.w + c.w;
        }
    }
    for (; p < e; p++) {
        unsigned pk = g_edge[p];
        const float4* hs = (const float4*)(g_h + (size_t)(pk & SRCMASK) * EMB);
        const float4* ct = &sctab[(pk >> 17) * 75];
        float4 h0 = norm(hs[i0], sc0, sh0), c0 = ct[i0];
        a0.x += h0.x + c0.x; a0.y += h0.y + c0.y; a0.z += h0.z + c0.z; a0.w += h0.w + c0.w;
        float4 h1 = norm(hs[i1], sc1, sh1), c1 = ct[i1];
        a1.x += h1.x + c1.x; a1.y += h1.y + c1.y; a1.z += h1.z + c1.z; a1.w += h1.w + c1.w;
        if (lane < 11) {
            float4 h2 = norm(hs[i2], sc2, sh2), c2 = ct[i2];
            a2.x += h2.x + c2.x; a2.y += h2.y + c2.y; a2.z += h2.z + c2.z; a2.w += h2.w + c2.w;
        }
    }
    auto rnd4 = [](float4 v) {
        return make_float4(tf32r(v.x), tf32r(v.y), tf32r(v.z), tf32r(v.w));
    };
    float4* ag = (float4*)(g_agg + (size_t)node * EMB);
    ag[i0] = rnd4(a0);
    ag[i1] = rnd4(a1);
    if (lane < 11) ag[i2] = rnd4(a2);
}

// ---------------- BatchNorm ----------------
__global__ void bn_zero_k() {
    int i = threadIdx.x;
    if (i < EMB) { g_bnsum[i] = 0.f; g_bnsq[i] = 0.f; }
}
__global__ void bnfin_k(const float* __restrict__ gamma,
                        const float* __restrict__ beta) {
    int f = threadIdx.x;
    if (f >= EMB) return;
    float m   = g_bnsum[f] * (1.f / NN);
    float var = g_bnsq[f] * (1.f / NN) - m * m;
    float sc  = rsqrtf(var + EPSV) * gamma[f];
    g_bnscale[f] = sc;
    g_bnshift[f] = beta[f] - m * sc;
}
__global__ void bn_apply_k() {
    long long i = (long long)blockIdx.x * blockDim.x + threadIdx.x;
    if (i >= (long long)NN * EMB) return;
    int f = (int)(i % EMB);
    g_h[i] = tf32r(fmaxf(fmaf(g_h[i], g_bnscale[f], g_bnshift[f]), 0.f));
}

// ---------------- pooling ----------------
__global__ void start_init_k() {
    int g = blockIdx.x * blockDim.x + threadIdx.x;
    if (g <= GG) g_start[g] = NN;
}
__global__ void bounds_k(const int* __restrict__ batch) {
    int r = blockIdx.x * blockDim.x + threadIdx.x;
    if (r >= NN) return;
    int b = batch[r];
    int pb = (r == 0) ? -1 : batch[r - 1];
    for (int g = pb + 1; g <= b; g++) g_start[g] = r;
}
__global__ void __launch_bounds__(256)
pool_g_k(float* __restrict__ out) {
    int g = blockIdx.x, f = threadIdx.x;
    int s = g_start[g], e = g_start[g + 1];
    float acc = 0.f;
    for (int r = s; r < e; r++) acc += g_hf[(size_t)r * FEATD + f];
    float c = fmaxf((float)(e - s), 1.f);
    float v = acc / c;
    out[(size_t)g * FEATD + f] = v;
    g_pool[(size_t)g * FEATD + f] = v;
}

// head
__global__ void __launch_bounds__(128)
pred_k(const float* __restrict__ pw1, const float* __restrict__ pb1,
       const float* __restrict__ pw2, const float* __restrict__ pb2,
       float* __restrict__ out) {
    __shared__ float sp[FEATD];
    __shared__ float sh[128];
    int g = blockIdx.x, t = threadIdx.x;
    sp[t]       = g_pool[(size_t)g * FEATD + t];
    sp[t + 128] = g_pool[(size_t)g * FEATD + t + 128];
    __syncthreads();
    float acc = pb1[t];
    for (int k = 0; k < FEATD; k++) acc = fmaf(sp[k], pw1[k * 128 + t], acc);
    sh[t] = fmaxf(acc, 0.f);
    __syncthreads();
    if (t < 2) {
        float a = pb2[t];
        for (int k = 0; k < 128; k++) a = fmaf(sh[k], pw2[k * 2 + t], a);
        out[(size_t)GG * FEATD + g * 2 + t] = a;
    }
}

// ---------------- launch ----------------
extern "C" void kernel_launch(void* const* d_in, const int* in_sizes, int n_in,
                              void* d_out, int out_size) {
    const int*   x     = (const int*)d_in[0];
    const int*   ei    = (const int*)d_in[1];
    const int*   ea    = (const int*)d_in[2];
    const int*   batch = (const int*)d_in[3];
    const float* xemb1 = (const float*)d_in[4];
    const float* xemb2 = (const float*)d_in[5];
    const float* ee1   = (const float*)d_in[6];
    const float* ee2   = (const float*)d_in[7];
    const float* w1    = (const float*)d_in[8];
    const float* b1    = (const float*)d_in[9];
    const float* w2    = (const float*)d_in[10];
    const float* b2    = (const float*)d_in[11];
    const float* gamma = (const float*)d_in[12];
    const float* beta  = (const float*)d_in[13];
    const float* fw    = (const float*)d_in[14];
    const float* fb    = (const float*)d_in[15];
    const float* pw1   = (const float*)d_in[16];
    const float* pb1   = (const float*)d_in[17];
    const float* pw2   = (const float*)d_in[18];
    const float* pb2   = (const float*)d_in[19];
    float* out = (float*)d_out;

    float *p_h, *p_agg, *p_hidden, *p_hf, *p_wbuf;
    cudaGetSymbolAddress((void**)&p_h, g_h);
    cudaGetSymbolAddress((void**)&p_agg, g_agg);
    cudaGetSymbolAddress((void**)&p_hidden, g_hidden);
    cudaGetSymbolAddress((void**)&p_hf, g_hf);
    cudaGetSymbolAddress((void**)&p_wbuf, g_wbuf);

    const long long nelem = (long long)NN * EMB;
    const int T = 256;
    const int gNE = (int)((nelem + T - 1) / T);
    const int MB = (NN + 127) / 128;
    const int NB_SCAN = (NN + 1023) / 1024;
    dim3 tb(32, 8);

    embed_k<<<gNE, T>>>(x, xemb1, xemb2);

    deg_zero_k<<<(NN + T - 1) / T, T>>>();
    deg_count_k<<<(EE + T - 1) / T, T>>>(ei);
    scan1_k<<<NB_SCAN, 256>>>();
    scan2_k<<<1, 32>>>(NB_SCAN);
    scan3_k<<<(NN + T - 1) / T, T>>>();
    fill_k<<<(EE + T - 1) / T, T>>>(ei, ea);

    for (int l = 0; l < LL; l++) {
        const float* ee1l = ee1 + (size_t)l * 6 * EMB;
        const float* ee2l = ee2 + (size_t)l * 3 * EMB;
        ctab_k<<<(18 * EMB + T - 1) / T, T>>>(ee1l, ee2l);
        if (l == 0) gather_k<false><<<(NN + 7) / 8, 256>>>();
        else        gather_k<true><<<(NN + 7) / 8, 256>>>();

        bn_zero_k<<<1, 320>>>();

        // GEMM1: [NN,300] @ [300,600], relu, tf32-rounded output
        wt_k<<<dim3((H2 + 31) / 32, (EMB + 31) / 32), tb>>>(w1 + (size_t)l * EMB * H2, EMB, H2);
        mgemm_k<true, true, false><<<dim3((H2 + 127) / 128, MB), 256>>>(
            p_agg, p_wbuf, b1 + (size_t)l * H2, p_hidden, NN, EMB, H2);
        // GEMM2: [NN,600] @ [600,300], BN stats fused in epilogue
        wt_k<<<dim3((EMB + 31) / 32, (H2 + 31) / 32), tb>>>(w2 + (size_t)l * H2 * EMB, H2, EMB);
        mgemm_k<false, false, true><<<dim3((EMB + 127) / 128, MB), 256>>>(
            p_hidden, p_wbuf, b2 + (size_t)l * EMB, p_h, NN, H2, EMB);

        bnfin_k<<<1, 320>>>(gamma + (size_t)l * EMB, beta + (size_t)l * EMB);
    }

    bn_apply_k<<<gNE, T>>>();
    wt_k<<<dim3((FEATD + 31) / 32, (EMB + 31) / 32), tb>>>(fw, EMB, FEATD);
    mgemm_k<false, false, false><<<dim3((FEATD + 127) / 128, MB), 256>>>(
        p_h, p_wbuf, fb, p_hf, NN, EMB, FEATD);

    start_init_k<<<(GG + 1 + T - 1) / T, T>>>();
    bounds_k<<<(NN + T - 1) / T, T>>>(batch);
    pool_g_k<<<GG, FEATD>>>(out);
    pred_k<<<GG, 128>>>(pw1, pb1, pw2, pb2, out);
}

// round 14
// speedup vs baseline: 1.1847x; 1.0038x over previous
#include <cuda_runtime.h>
#include <cuda_bf16.h>
#include <cuda_pipeline_primitives.h>
#include <cstdio>
#include <cstdint>

#define NN 100000
#define EE 500000
#define GG 2000
#define LL 5
#define EMB 300
#define H2  600
#define FEATD 256
#define EPSV 1e-5f
#define SRCMASK 0x1FFFF

// ---------------- scratch (device globals; no allocs allowed) ----------------
__device__ float g_h[(size_t)NN * EMB];
__device__ float g_agg[(size_t)NN * EMB];
__device__ float g_hidden[(size_t)NN * H2];
__device__ float g_hf[(size_t)NN * FEATD];
__device__ float g_bnsum[EMB];
__device__ float g_bnsq[EMB];
__device__ float g_bnscale[EMB];
__device__ float g_bnshift[EMB];
__device__ float g_pool[(size_t)GG * FEATD];
__device__ float g_ctab[18 * EMB];
__device__ float g_wbuf[EMB * H2];     // K-major tf32-rounded weights [Ncol, K]
// CSR scratch
__device__ int g_deg[NN];
__device__ int g_off[NN + 1];
__device__ int g_fill[NN];
__device__ unsigned g_edge[EE];
__device__ int g_part[128];
__device__ int g_start[GG + 1];

// ---------------- helpers ----------------
__device__ __forceinline__ float tf32r(float x) {
    float y;
    asm("cvt.rna.tf32.f32 %0, %1;" : "=f"(y) : "f"(x));
    return y;
}
__device__ __forceinline__ uint32_t smem_u32(const void* p) {
    uint32_t a;
    asm("{ .reg .u64 t; cvta.to.shared.u64 t, %1; cvt.u32.u64 %0, t; }"
        : "=r"(a) : "l"(p));
    return a;
}
#define LDSM4(r, addr) \
    asm volatile("ldmatrix.sync.aligned.m8n8.x4.shared.b16 {%0,%1,%2,%3}, [%4];" \
                 : "=r"((r)[0]), "=r"((r)[1]), "=r"((r)[2]), "=r"((r)[3]) \
                 : "r"(addr))
#define MMA_TF32(d, a, b0, b1) \
    asm volatile("mma.sync.aligned.m16n8k8.row.col.f32.tf32.tf32.f32 " \
                 "{%0,%1,%2,%3}, {%4,%5,%6,%7}, {%8,%9}, {%0,%1,%2,%3};" \
                 : "+f"((d)[0]), "+f"((d)[1]), "+f"((d)[2]), "+f"((d)[3]) \
                 : "r"((a)[0]), "r"((a)[1]), "r"((a)[2]), "r"((a)[3]), \
                   "r"(b0), "r"(b1))

// ======== tf32 mma GEMM: C[M,Ncol] = act(A[M,K] @ Bt[Ncol,K]^T + bias)
// Bt is K-major [Ncol,K] (tf32-rounded). BM=128 BN=128 BK=16, 128 thr,
// 4 warps as 2(M) x 2(N), warp tile 64x64 -> 8 LDSM : 32 MMA per k8.
#define ALD 20                     // padded floats per smem row (conflict-free LDSM)
#define STG_FLT (128 * ALD)        // 2560 floats = 10240 B per tile stage

template <bool RELU, bool ROUND_OUT, bool STATS>
__global__ void __launch_bounds__(128)
mgemm_k(const float* __restrict__ A, const float* __restrict__ Bt,
        const float* __restrict__ bias, float* __restrict__ C,
        int M, int K, int Ncol) {
    __shared__ __align__(16) float sA[2 * STG_FLT];
    __shared__ __align__(16) float sB[2 * STG_FLT];

    const int tid = threadIdx.x;
    const int warp = tid >> 5;
    const int lane = tid & 31;
    const int wm = warp & 1;       // 2 warp rows (64 each)
    const int wn = warp >> 1;      // 2 warp cols (64 each)
    const int bm = blockIdx.y * 128;
    const int bn = blockIdx.x * 128;

    const uint32_t sA_u = smem_u32(sA);
    const uint32_t sB_u = smem_u32(sB);

    // per-lane LDSM byte offsets within a stage
    uint32_t aoff[4], boff[4];
#pragma unroll
    for (int mi = 0; mi < 4; mi++) {
        int row = wm * 64 + mi * 16 + (lane & 15);
        int col = (lane >> 4) * 4;
        aoff[mi] = (uint32_t)((row * ALD + col) * 4);
    }
#pragma unroll
    for (int pj = 0; pj < 4; pj++) {
        int nrow = wn * 64 + pj * 16 + (lane & 7) + ((lane >> 4) << 3);
        int col  = ((lane >> 3) & 1) * 4;
        boff[pj] = (uint32_t)((nrow * ALD + col) * 4);
    }

    float acc[4][8][4];
#pragma unroll
    for (int i = 0; i < 4; i++)
#pragma unroll
        for (int j = 0; j < 8; j++)
#pragma unroll
            for (int e = 0; e < 4; e++) acc[i][j][e] = 0.f;

    const int KT = (K + 15) / 16;

    auto load_tiles = [&](int s, int k0) {
#pragma unroll
        for (int i = 0; i < 4; i++) {
            int t = tid + i * 128;              // 512 float4 tasks per tile
            int row = t >> 2, q = t & 3;
            int gk = k0 + q * 4;
            // A
            {
                int gm = bm + row; if (gm >= M) gm = M - 1;
                float* dst = &sA[s * STG_FLT + row * ALD + q * 4];
                if (gk < K)
                    __pipeline_memcpy_async(dst, &A[(size_t)gm * K + gk], 16);
                else { dst[0] = 0.f; dst[1] = 0.f; dst[2] = 0.f; dst[3] = 0.f; }
            }
            // B (rows are N)
            {
                int gn = bn + row; if (gn >= Ncol) gn = Ncol - 1;
                float* dst = &sB[s * STG_FLT + row * ALD + q * 4];
                if (gk < K)
                    __pipeline_memcpy_async(dst, &Bt[(size_t)gn * K + gk], 16);
                else { dst[0] = 0.f; dst[1] = 0.f; dst[2] = 0.f; dst[3] = 0.f; }
            }
        }
    };

    load_tiles(0, 0);
    __pipeline_commit();

    for (int kt = 0; kt < KT; kt++) {
        int s = kt & 1;
        bool has_next = (kt + 1 < KT);
        if (has_next) { load_tiles(s ^ 1, (kt + 1) * 16); __pipeline_commit(); }
        __pipeline_wait_prior(has_next ? 1 : 0);
        __syncthreads();

        uint32_t baseA = sA_u + s * (STG_FLT * 4);
        uint32_t baseB = sB_u + s * (STG_FLT * 4);
#pragma unroll
        for (int kk8 = 0; kk8 < 2; kk8++) {
            uint32_t a[4][4], b[4][4];
#pragma unroll
            for (int mi = 0; mi < 4; mi++)
                LDSM4(a[mi], baseA + aoff[mi] + kk8 * 32);
#pragma unroll
            for (int pj = 0; pj < 4; pj++)
                LDSM4(b[pj], baseB + boff[pj] + kk8 * 32);
#pragma unroll
            for (int mi = 0; mi < 4; mi++)
#pragma unroll
                for (int pj = 0; pj < 4; pj++) {
                    MMA_TF32(acc[mi][2 * pj],     a[mi], b[pj][0], b[pj][1]);
                    MMA_TF32(acc[mi][2 * pj + 1], a[mi], b[pj][2], b[pj][3]);
                }
        }
        __syncthreads();
    }

    // ---- direct register epilogue (known m16n8 C layout), optional BN stats --
    const int qr = lane >> 2;          // row within 8
    const int qc = 2 * (lane & 3);     // col pair base
#pragma unroll
    for (int nj = 0; nj < 8; nj++) {
        int gn = bn + wn * 64 + nj * 8 + qc;
        float s0 = 0.f, s1 = 0.f, q0 = 0.f, q1 = 0.f;
        if (gn < Ncol) {
            float2 bb = *(const float2*)&bias[gn];
#pragma unroll
            for (int mi = 0; mi < 4; mi++) {
                int gm0 = bm + wm * 64 + mi * 16 + qr;
                int gm1 = gm0 + 8;
                float* d = acc[mi][nj];
                if (gm0 < M) {
                    float v0 = d[0] + bb.x, v1 = d[1] + bb.y;
                    if (RELU) { v0 = fmaxf(v0, 0.f); v1 = fmaxf(v1, 0.f); }
                    if (STATS) { s0 += v0; s1 += v1; q0 += v0 * v0; q1 += v1 * v1; }
                    if (ROUND_OUT) { v0 = tf32r(v0); v1 = tf32r(v1); }
                    *(float2*)&C[(size_t)gm0 * Ncol + gn] = make_float2(v0, v1);
                }
                if (gm1 < M) {
                    float v2 = d[2] + bb.x, v3 = d[3] + bb.y;
                    if (RELU) { v2 = fmaxf(v2, 0.f); v3 = fmaxf(v3, 0.f); }
                    if (STATS) { s0 += v2; s1 += v3; q0 += v2 * v2; q1 += v3 * v3; }
                    if (ROUND_OUT) { v2 = tf32r(v2); v3 = tf32r(v3); }
                    *(float2*)&C[(size_t)gm1 * Ncol + gn] = make_float2(v2, v3);
                }
            }
        }
        if (STATS) {
            // reduce across lanes sharing the same column (lane & 3 groups)
#pragma unroll
            for (int off = 4; off < 32; off <<= 1) {
                s0 += __shfl_xor_sync(0xFFFFFFFF, s0, off);
                s1 += __shfl_xor_sync(0xFFFFFFFF, s1, off);
                q0 += __shfl_xor_sync(0xFFFFFFFF, q0, off);
                q1 += __shfl_xor_sync(0xFFFFFFFF, q1, off);
            }
            if (lane < 4) {
                int cgn = bn + wn * 64 + nj * 8 + 2 * lane;
                if (cgn < Ncol) {
                    atomicAdd(&g_bnsum[cgn],     s0);
                    atomicAdd(&g_bnsum[cgn + 1], s1);
                    atomicAdd(&g_bnsq[cgn],      q0);
                    atomicAdd(&g_bnsq[cgn + 1],  q1);
                }
            }
        }
    }
}

// ---------------- weight transpose+round: [K,Ncol] -> tf32 K-major [Ncol,K] --
__global__ void wt_k(const float* __restrict__ src, int K, int Ncol) {
    __shared__ float t[32][33];
    int bx = blockIdx.x * 32, by = blockIdx.y * 32;
    int x = bx + threadIdx.x;     // n
#pragma unroll
    for (int j = 0; j < 32; j += 8) {
        int y = by + threadIdx.y + j;   // k
        if (x < Ncol && y < K) t[threadIdx.y + j][threadIdx.x] = src[(size_t)y * Ncol + x];
    }
    __syncthreads();
    int xk = by + threadIdx.x;    // k
#pragma unroll
    for (int j = 0; j < 32; j += 8) {
        int yn = bx + threadIdx.y + j;  // n
        if (xk < K && yn < Ncol)
            g_wbuf[(size_t)yn * K + xk] = tf32r(t[threadIdx.x][threadIdx.y + j]);
    }
}

// ---------------- node embed ----------------
__global__ void embed_k(const int* __restrict__ x,
                        const float* __restrict__ e1,
                        const float* __restrict__ e2) {
    long long i = (long long)blockIdx.x * blockDim.x + threadIdx.x;
    if (i >= (long long)NN * EMB) return;
    int r = (int)(i / EMB);
    int f = (int)(i - (long long)r * EMB);
    g_h[i] = e1[x[2 * r] * EMB + f] + e2[x[2 * r + 1] * EMB + f];
}

// ---------------- CSR build (once per call) ----------------
__global__ void deg_zero_k() {
    int i = blockIdx.x * blockDim.x + threadIdx.x;
    if (i < NN) g_deg[i] = 0;
}
__global__ void deg_count_k(const int* __restrict__ ei) {
    int e = blockIdx.x * blockDim.x + threadIdx.x;
    if (e < EE) atomicAdd(&g_deg[ei[EE + e]], 1);
}
__global__ void scan1_k() {
    __shared__ int ssum[256];
    int tid = threadIdx.x;
    int base = blockIdx.x * 1024;
    int v[4]; int tot = 0;
#pragma unroll
    for (int i = 0; i < 4; i++) {
        int idx = base + tid * 4 + i;
        v[i] = (idx < NN) ? g_deg[idx] : 0;
        tot += v[i];
    }
    ssum[tid] = tot;
    __syncthreads();
    for (int off = 1; off < 256; off <<= 1) {
        int t = (tid >= off) ? ssum[tid - off] : 0;
        __syncthreads();
        ssum[tid] += t;
        __syncthreads();
    }
    int run = ssum[tid] - tot;
#pragma unroll
    for (int i = 0; i < 4; i++) {
        int idx = base + tid * 4 + i;
        if (idx < NN) g_off[idx] = run;
        run += v[i];
    }
    if (tid == 255) g_part[blockIdx.x] = ssum[255];
}
__global__ void scan2_k(int nb) {
    if (threadIdx.x == 0) {
        int run = 0;
        for (int b = 0; b < nb; b++) { int t = g_part[b]; g_part[b] = run; run += t; }
    }
}
__global__ void scan3_k() {
    int i = blockIdx.x * blockDim.x + threadIdx.x;
    if (i < NN) {
        int o = g_off[i] + g_part[i >> 10];
        g_off[i] = o;
        g_fill[i] = o;
    }
    if (i == 0) g_off[NN] = EE;
}
__global__ void fill_k(const int* __restrict__ ei, const int* __restrict__ ea) {
    int e = blockIdx.x * blockDim.x + threadIdx.x;
    if (e >= EE) return;
    int s = ei[e];
    int d = ei[EE + e];
    unsigned combo = (unsigned)(ea[2 * e] * 3 + ea[2 * e + 1]);
    int pos = atomicAdd(&g_fill[d], 1);
    g_edge[pos] = (unsigned)s | (combo << 17);
}

// ---------------- per-layer combo table ----------------
__global__ void ctab_k(const float* __restrict__ ee1l, const float* __restrict__ ee2l) {
    int i = blockIdx.x * blockDim.x + threadIdx.x;
    if (i >= 18 * EMB) return;
    int combo = i / EMB, f = i - combo * EMB;
    g_ctab[i] = ee1l[(combo / 3) * EMB + f] + ee2l[(combo % 3) * EMB + f];
}

// ---------------- gather: warp/node, BN+ReLU fused, tf32-rounded out --------
template <bool BN>
__global__ void __launch_bounds__(256)
gather_k() {
    __shared__ float4 sctab[18 * EMB / 4];
    __shared__ float4 ssc[EMB / 4 + 1];
    __shared__ float4 ssh[EMB / 4 + 1];
    int tid = threadIdx.x;
    const float4* gt = (const float4*)g_ctab;
    for (int i = tid; i < 18 * EMB / 4; i += 256) sctab[i] = gt[i];
    if (BN) {
        const float4* sc = (const float4*)g_bnscale;
        const float4* sh = (const float4*)g_bnshift;
        for (int i = tid; i < EMB / 4; i += 256) { ssc[i] = sc[i]; ssh[i] = sh[i]; }
    }
    __syncthreads();
    int node = blockIdx.x * 8 + (tid >> 5);
    if (node >= NN) return;
    int lane = tid & 31;
    int i0 = lane, i1 = lane + 32, i2 = lane + 64;
    float4 sc0, sc1, sc2, sh0, sh1, sh2;
    if (BN) {
        sc0 = ssc[i0]; sh0 = ssh[i0];
        sc1 = ssc[i1]; sh1 = ssh[i1];
        if (lane < 11) { sc2 = ssc[i2]; sh2 = ssh[i2]; }
    }
    auto norm = [&](float4 h, const float4& sc, const float4& sh) -> float4 {
        if (!BN) return h;
        return make_float4(fmaxf(fmaf(h.x, sc.x, sh.x), 0.f),
                           fmaxf(fmaf(h.y, sc.y, sh.y), 0.f),
                           fmaxf(fmaf(h.z, sc.z, sh.z), 0.f),
                           fmaxf(fmaf(h.w, sc.w, sh.w), 0.f));
    };
    float4 a0, a1, a2;
    {
        const float4* hn = (const float4*)(g_h + (size_t)node * EMB);
        const float4* self = &sctab[12 * 75];
        float4 h0 = norm(hn[i0], sc0, sh0), c0 = self[i0];
        float4 h1 = norm(hn[i1], sc1, sh1), c1 = self[i1];
        a0 = make_float4(h0.x + c0.x, h0.y + c0.y, h0.z + c0.z, h0.w + c0.w);
        a1 = make_float4(h1.x + c1.x, h1.y + c1.y, h1.z + c1.z, h1.w + c1.w);
        a2 = make_float4(0.f, 0.f, 0.f, 0.f);
        if (lane < 11) {
            float4 h2 = norm(hn[i2], sc2, sh2), c2 = self[i2];
            a2 = make_float4(h2.x + c2.x, h2.y + c2.y, h2.z + c2.z, h2.w + c2.w);
        }
    }
    int s = g_off[node], e = g_off[node + 1];
    int p = s;
    for (; p + 1 < e; p += 2) {
        unsigned pka = g_edge[p], pkb = g_edge[p + 1];
        const float4* ha = (const float4*)(g_h + (size_t)(pka & SRCMASK) * EMB);
        const float4* hb = (const float4*)(g_h + (size_t)(pkb & SRCMASK) * EMB);
        const float4* ca = &sctab[(pka >> 17) * 75];
        const float4* cb = &sctab[(pkb >> 17) * 75];
        float4 ha0 = ha[i0], hb0 = hb[i0];
        float4 ha1 = ha[i1], hb1 = hb[i1];
        float4 ha2, hb2;
        if (lane < 11) { ha2 = ha[i2]; hb2 = hb[i2]; }
        ha0 = norm(ha0, sc0, sh0); hb0 = norm(hb0, sc0, sh0);
        ha1 = norm(ha1, sc1, sh1); hb1 = norm(hb1, sc1, sh1);
        float4 c;
        c = ca[i0]; a0.x += ha0.x + c.x; a0.y += ha0.y + c.y; a0.z += ha0.z + c.z; a0.w += ha0.w + c.w;
        c = cb[i0]; a0.x += hb0.x + c.x; a0.y += hb0.y + c.y; a0.z += hb0.z + c.z; a0.w += hb0.w + c.w;
        c = ca[i1]; a1.x += ha1.x + c.x; a1.y += ha1.y + c.y; a1.z += ha1.z + c.z; a1.w += ha1.w + c.w;
        c = cb[i1]; a1.x += hb1.x + c.x; a1.y += hb1.y + c.y; a1.z += hb1.z + c.z; a1.w += hb1.w + c.w;
        if (lane < 11) {
            ha2 = norm(ha2, sc2, sh2); hb2 = norm(hb2, sc2, sh2);
            c = ca[i2]; a2.x += ha2.x + c.x; a2.y += ha2.y + c.y; a2.z += ha2.z + c.z; a2.w += ha2.w + c.w;
            c = cb[i2]; a2.x += hb2.x + c.x; a2.y += hb2.y + c.y; a2.z += hb2.z + c.z; a2.w += hb2.w + c.w;
        }
    }
    for (; p < e; p++) {
        unsigned pk = g_edge[p];
        const float4* hs = (const float4*)(g_h + (size_t)(pk & SRCMASK) * EMB);
        const float4* ct = &sctab[(pk >> 17) * 75];
        float4 h0 = norm(hs[i0], sc0, sh0), c0 = ct[i0];
        a0.x += h0.x + c0.x; a0.y += h0.y + c0.y; a0.z += h0.z + c0.z; a0.w += h0.w + c0.w;
        float4 h1 = norm(hs[i1], sc1, sh1), c1 = ct[i1];
        a1.x += h1.x + c1.x; a1.y += h1.y + c1.y; a1.z += h1.z + c1.z; a1.w += h1.w + c1.w;
        if (lane < 11) {
            float4 h2 = norm(hs[i2], sc2, sh2), c2 = ct[i2];
            a2.x += h2.x + c2.x; a2.y += h2.y + c2.y; a2.z += h2.z + c2.z; a2.w += h2.w + c2.w;
        }
    }
    auto rnd4 = [](float4 v) {
        return make_float4(tf32r(v.x), tf32r(v.y), tf32r(v.z), tf32r(v.w));
    };
    float4* ag = (float4*)(g_agg + (size_t)node * EMB);
    ag[i0] = rnd4(a0);
    ag[i1] = rnd4(a1);
    if (lane < 11) ag[i2] = rnd4(a2);
}

// ---------------- BatchNorm ----------------
__global__ void bn_zero_k() {
    int i = threadIdx.x;
    if (i < EMB) { g_bnsum[i] = 0.f; g_bnsq[i] = 0.f; }
}
__global__ void bnfin_k(const float* __restrict__ gamma,
                        const float* __restrict__ beta) {
    int f = threadIdx.x;
    if (f >= EMB) return;
    float m   = g_bnsum[f] * (1.f / NN);
    float var = g_bnsq[f] * (1.f / NN) - m * m;
    float sc  = rsqrtf(var + EPSV) * gamma[f];
    g_bnscale[f] = sc;
    g_bnshift[f] = beta[f] - m * sc;
}
__global__ void bn_apply_k() {
    long long i = (long long)blockIdx.x * blockDim.x + threadIdx.x;
    if (i >= (long long)NN * EMB) return;
    int f = (int)(i % EMB);
    g_h[i] = tf32r(fmaxf(fmaf(g_h[i], g_bnscale[f], g_bnshift[f]), 0.f));
}

// ---------------- pooling ----------------
__global__ void start_init_k() {
    int g = blockIdx.x * blockDim.x + threadIdx.x;
    if (g <= GG) g_start[g] = NN;
}
__global__ void bounds_k(const int* __restrict__ batch) {
    int r = blockIdx.x * blockDim.x + threadIdx.x;
    if (r >= NN) return;
    int b = batch[r];
    int pb = (r == 0) ? -1 : batch[r - 1];
    for (int g = pb + 1; g <= b; g++) g_start[g] = r;
}
__global__ void __launch_bounds__(256)
pool_g_k(float* __restrict__ out) {
    int g = blockIdx.x, f = threadIdx.x;
    int s = g_start[g], e = g_start[g + 1];
    float acc = 0.f;
    for (int r = s; r < e; r++) acc += g_hf[(size_t)r * FEATD + f];
    float c = fmaxf((float)(e - s), 1.f);
    float v = acc / c;
    out[(size_t)g * FEATD + f] = v;
    g_pool[(size_t)g * FEATD + f] = v;
}

// head
__global__ void __launch_bounds__(128)
pred_k(const float* __restrict__ pw1, const float* __restrict__ pb1,
       const float* __restrict__ pw2, const float* __restrict__ pb2,
       float* __restrict__ out) {
    __shared__ float sp[FEATD];
    __shared__ float sh[128];
    int g = blockIdx.x, t = threadIdx.x;
    sp[t]       = g_pool[(size_t)g * FEATD + t];
    sp[t + 128] = g_pool[(size_t)g * FEATD + t + 128];
    __syncthreads();
    float acc = pb1[t];
    for (int k = 0; k < FEATD; k++) acc = fmaf(sp[k], pw1[k * 128 + t], acc);
    sh[t] = fmaxf(acc, 0.f);
    __syncthreads();
    if (t < 2) {
        float a = pb2[t];
        for (int k = 0; k < 128; k++) a = fmaf(sh[k], pw2[k * 2 + t], a);
        out[(size_t)GG * FEATD + g * 2 + t] = a;
    }
}

// ---------------- launch ----------------
extern "C" void kernel_launch(void* const* d_in, const int* in_sizes, int n_in,
                              void* d_out, int out_size) {
    const int*   x     = (const int*)d_in[0];
    const int*   ei    = (const int*)d_in[1];
    const int*   ea    = (const int*)d_in[2];
    const int*   batch = (const int*)d_in[3];
    const float* xemb1 = (const float*)d_in[4];
    const float* xemb2 = (const float*)d_in[5];
    const float* ee1   = (const float*)d_in[6];
    const float* ee2   = (const float*)d_in[7];
    const float* w1    = (const float*)d_in[8];
    const float* b1    = (const float*)d_in[9];
    const float* w2    = (const float*)d_in[10];
    const float* b2    = (const float*)d_in[11];
    const float* gamma = (const float*)d_in[12];
    const float* beta  = (const float*)d_in[13];
    const float* fw    = (const float*)d_in[14];
    const float* fb    = (const float*)d_in[15];
    const float* pw1   = (const float*)d_in[16];
    const float* pb1   = (const float*)d_in[17];
    const float* pw2   = (const float*)d_in[18];
    const float* pb2   = (const float*)d_in[19];
    float* out = (float*)d_out;

    float *p_h, *p_agg, *p_hidden, *p_hf, *p_wbuf;
    cudaGetSymbolAddress((void**)&p_h, g_h);
    cudaGetSymbolAddress((void**)&p_agg, g_agg);
    cudaGetSymbolAddress((void**)&p_hidden, g_hidden);
    cudaGetSymbolAddress((void**)&p_hf, g_hf);
    cudaGetSymbolAddress((void**)&p_wbuf, g_wbuf);

    const long long nelem = (long long)NN * EMB;
    const int T = 256;
    const int gNE = (int)((nelem + T - 1) / T);
    const int MB = (NN + 127) / 128;
    const int NB_SCAN = (NN + 1023) / 1024;
    dim3 tb(32, 8);

    embed_k<<<gNE, T>>>(x, xemb1, xemb2);

    deg_zero_k<<<(NN + T - 1) / T, T>>>();
    deg_count_k<<<(EE + T - 1) / T, T>>>(ei);
    scan1_k<<<NB_SCAN, 256>>>();
    scan2_k<<<1, 32>>>(NB_SCAN);
    scan3_k<<<(NN + T - 1) / T, T>>>();
    fill_k<<<(EE + T - 1) / T, T>>>(ei, ea);

    for (int l = 0; l < LL; l++) {
        const float* ee1l = ee1 + (size_t)l * 6 * EMB;
        const float* ee2l = ee2 + (size_t)l * 3 * EMB;
        ctab_k<<<(18 * EMB + T - 1) / T, T>>>(ee1l, ee2l);
        if (l == 0) gather_k<false><<<(NN + 7) / 8, 256>>>();
        else        gather_k<true><<<(NN + 7) / 8, 256>>>();

        bn_zero_k<<<1, 320>>>();

        // GEMM1: [NN,300] @ [300,600], relu, tf32-rounded output
        wt_k<<<dim3((H2 + 31) / 32, (EMB + 31) / 32), tb>>>(w1 + (size_t)l * EMB * H2, EMB, H2);
        mgemm_k<true, true, false><<<dim3((H2 + 127) / 128, MB), 128>>>(
            p_agg, p_wbuf, b1 + (size_t)l * H2, p_hidden, NN, EMB, H2);
        // GEMM2: [NN,600] @ [600,300], BN stats fused in epilogue
        wt_k<<<dim3((EMB + 31) / 32, (H2 + 31) / 32), tb>>>(w2 + (size_t)l * H2 * EMB, H2, EMB);
        mgemm_k<false, false, true><<<dim3((EMB + 127) / 128, MB), 128>>>(
            p_hidden, p_wbuf, b2 + (size_t)l * EMB, p_h, NN, H2, EMB);

        bnfin_k<<<1, 320>>>(gamma + (size_t)l * EMB, beta + (size_t)l * EMB);
    }

    bn_apply_k<<<gNE, T>>>();
    wt_k<<<dim3((FEATD + 31) / 32, (EMB + 31) / 32), tb>>>(fw, EMB, FEATD);
    mgemm_k<false, false, false><<<dim3((FEATD + 127) / 128, MB), 128>>>(
        p_h, p_wbuf, fb, p_hf, NN, EMB, FEATD);

    start_init_k<<<(GG + 1 + T - 1) / T, T>>>();
    bounds_k<<<(NN + T - 1) / T, T>>>(batch);
    pool_g_k<<<GG, FEATD>>>(out);
    pred_k<<<GG, 128>>>(pw1, pb1, pw2, pb2, out);
}

// round 15
// speedup vs baseline: 1.2297x; 1.0380x over previous
#include <cuda_runtime.h>
#include <cuda_bf16.h>
#include <cuda_pipeline_primitives.h>
#include <cstdio>
#include <cstdint>

#define NN 100000
#define EE 500000
#define GG 2000
#define LL 5
#define EMB 300
#define H2  600
#define FEATD 256
#define EPSV 1e-5f
#define SRCMASK 0x1FFFF

// ---------------- scratch (device globals; no allocs allowed) ----------------
__device__ float g_h[(size_t)NN * EMB];
__device__ float g_agg[(size_t)NN * EMB];
__device__ float g_hidden[(size_t)NN * H2];
__device__ float g_hm[(size_t)GG * EMB];        // per-graph mean of h
__device__ float g_bnsum[EMB];
__device__ float g_bnsq[EMB];
__device__ float g_bnscale[EMB];
__device__ float g_bnshift[EMB];
__device__ float g_ctab[18 * EMB];
__device__ float g_w1t[(size_t)LL * H2 * EMB];  // transposed tf32 weights
__device__ float g_w2t[(size_t)LL * EMB * H2];
__device__ float g_fwt[(size_t)FEATD * EMB];
// CSR scratch
__device__ int g_deg[NN];
__device__ int g_off[NN + 1];
__device__ int g_fill[NN];
__device__ unsigned g_edge[EE];
__device__ int g_part[128];
__device__ int g_start[GG + 1];

// ---------------- helpers ----------------
__device__ __forceinline__ float tf32r(float x) {
    float y;
    asm("cvt.rna.tf32.f32 %0, %1;" : "=f"(y) : "f"(x));
    return y;
}
__device__ __forceinline__ uint32_t smem_u32(const void* p) {
    uint32_t a;
    asm("{ .reg .u64 t; cvta.to.shared.u64 t, %1; cvt.u32.u64 %0, t; }"
        : "=r"(a) : "l"(p));
    return a;
}
#define LDSM4(r, addr) \
    asm volatile("ldmatrix.sync.aligned.m8n8.x4.shared.b16 {%0,%1,%2,%3}, [%4];" \
                 : "=r"((r)[0]), "=r"((r)[1]), "=r"((r)[2]), "=r"((r)[3]) \
                 : "r"(addr))
#define MMA_TF32(d, a, b0, b1) \
    asm volatile("mma.sync.aligned.m16n8k8.row.col.f32.tf32.tf32.f32 " \
                 "{%0,%1,%2,%3}, {%4,%5,%6,%7}, {%8,%9}, {%0,%1,%2,%3};" \
                 : "+f"((d)[0]), "+f"((d)[1]), "+f"((d)[2]), "+f"((d)[3]) \
                 : "r"((a)[0]), "r"((a)[1]), "r"((a)[2]), "r"((a)[3]), \
                   "r"(b0), "r"(b1))

// ======== tf32 mma GEMM: C[M,Ncol] = act(A[M,K] @ Bt[Ncol,K]^T + bias)
// Bt is K-major [Ncol,K] (tf32-rounded). BM=128 BN=128 BK=16, 128 thr,
// 4 warps as 2(M) x 2(N), warp tile 64x64. (round-14 config)
#define ALD 20
#define STG_FLT (128 * ALD)

template <bool RELU, bool ROUND_OUT, bool STATS>
__global__ void __launch_bounds__(128)
mgemm_k(const float* __restrict__ A, const float* __restrict__ Bt,
        const float* __restrict__ bias, float* __restrict__ C,
        int M, int K, int Ncol) {
    __shared__ __align__(16) float sA[2 * STG_FLT];
    __shared__ __align__(16) float sB[2 * STG_FLT];

    const int tid = threadIdx.x;
    const int warp = tid >> 5;
    const int lane = tid & 31;
    const int wm = warp & 1;
    const int wn = warp >> 1;
    const int bm = blockIdx.y * 128;
    const int bn = blockIdx.x * 128;

    const uint32_t sA_u = smem_u32(sA);
    const uint32_t sB_u = smem_u32(sB);

    uint32_t aoff[4], boff[4];
#pragma unroll
    for (int mi = 0; mi < 4; mi++) {
        int row = wm * 64 + mi * 16 + (lane & 15);
        int col = (lane >> 4) * 4;
        aoff[mi] = (uint32_t)((row * ALD + col) * 4);
    }
#pragma unroll
    for (int pj = 0; pj < 4; pj++) {
        int nrow = wn * 64 + pj * 16 + (lane & 7) + ((lane >> 4) << 3);
        int col  = ((lane >> 3) & 1) * 4;
        boff[pj] = (uint32_t)((nrow * ALD + col) * 4);
    }

    float acc[4][8][4];
#pragma unroll
    for (int i = 0; i < 4; i++)
#pragma unroll
        for (int j = 0; j < 8; j++)
#pragma unroll
            for (int e = 0; e < 4; e++) acc[i][j][e] = 0.f;

    const int KT = (K + 15) / 16;

    auto load_tiles = [&](int s, int k0) {
#pragma unroll
        for (int i = 0; i < 4; i++) {
            int t = tid + i * 128;
            int row = t >> 2, q = t & 3;
            int gk = k0 + q * 4;
            {
                int gm = bm + row; if (gm >= M) gm = M - 1;
                float* dst = &sA[s * STG_FLT + row * ALD + q * 4];
                if (gk < K)
                    __pipeline_memcpy_async(dst, &A[(size_t)gm * K + gk], 16);
                else { dst[0] = 0.f; dst[1] = 0.f; dst[2] = 0.f; dst[3] = 0.f; }
            }
            {
                int gn = bn + row; if (gn >= Ncol) gn = Ncol - 1;
                float* dst = &sB[s * STG_FLT + row * ALD + q * 4];
                if (gk < K)
                    __pipeline_memcpy_async(dst, &Bt[(size_t)gn * K + gk], 16);
                else { dst[0] = 0.f; dst[1] = 0.f; dst[2] = 0.f; dst[3] = 0.f; }
            }
        }
    };

    load_tiles(0, 0);
    __pipeline_commit();

    for (int kt = 0; kt < KT; kt++) {
        int s = kt & 1;
        bool has_next = (kt + 1 < KT);
        if (has_next) { load_tiles(s ^ 1, (kt + 1) * 16); __pipeline_commit(); }
        __pipeline_wait_prior(has_next ? 1 : 0);
        __syncthreads();

        uint32_t baseA = sA_u + s * (STG_FLT * 4);
        uint32_t baseB = sB_u + s * (STG_FLT * 4);
#pragma unroll
        for (int kk8 = 0; kk8 < 2; kk8++) {
            uint32_t a[4][4], b[4][4];
#pragma unroll
            for (int mi = 0; mi < 4; mi++)
                LDSM4(a[mi], baseA + aoff[mi] + kk8 * 32);
#pragma unroll
            for (int pj = 0; pj < 4; pj++)
                LDSM4(b[pj], baseB + boff[pj] + kk8 * 32);
#pragma unroll
            for (int mi = 0; mi < 4; mi++)
#pragma unroll
                for (int pj = 0; pj < 4; pj++) {
                    MMA_TF32(acc[mi][2 * pj],     a[mi], b[pj][0], b[pj][1]);
                    MMA_TF32(acc[mi][2 * pj + 1], a[mi], b[pj][2], b[pj][3]);
                }
        }
        __syncthreads();
    }

    const int qr = lane >> 2;
    const int qc = 2 * (lane & 3);
#pragma unroll
    for (int nj = 0; nj < 8; nj++) {
        int gn = bn + wn * 64 + nj * 8 + qc;
        float s0 = 0.f, s1 = 0.f, q0 = 0.f, q1 = 0.f;
        if (gn < Ncol) {
            float2 bb = *(const float2*)&bias[gn];
#pragma unroll
            for (int mi = 0; mi < 4; mi++) {
                int gm0 = bm + wm * 64 + mi * 16 + qr;
                int gm1 = gm0 + 8;
                float* d = acc[mi][nj];
                if (gm0 < M) {
                    float v0 = d[0] + bb.x, v1 = d[1] + bb.y;
                    if (RELU) { v0 = fmaxf(v0, 0.f); v1 = fmaxf(v1, 0.f); }
                    if (STATS) { s0 += v0; s1 += v1; q0 += v0 * v0; q1 += v1 * v1; }
                    if (ROUND_OUT) { v0 = tf32r(v0); v1 = tf32r(v1); }
                    *(float2*)&C[(size_t)gm0 * Ncol + gn] = make_float2(v0, v1);
                }
                if (gm1 < M) {
                    float v2 = d[2] + bb.x, v3 = d[3] + bb.y;
                    if (RELU) { v2 = fmaxf(v2, 0.f); v3 = fmaxf(v3, 0.f); }
                    if (STATS) { s0 += v2; s1 += v3; q0 += v2 * v2; q1 += v3 * v3; }
                    if (ROUND_OUT) { v2 = tf32r(v2); v3 = tf32r(v3); }
                    *(float2*)&C[(size_t)gm1 * Ncol + gn] = make_float2(v2, v3);
                }
            }
        }
        if (STATS) {
#pragma unroll
            for (int off = 4; off < 32; off <<= 1) {
                s0 += __shfl_xor_sync(0xFFFFFFFF, s0, off);
                s1 += __shfl_xor_sync(0xFFFFFFFF, s1, off);
                q0 += __shfl_xor_sync(0xFFFFFFFF, q0, off);
                q1 += __shfl_xor_sync(0xFFFFFFFF, q1, off);
            }
            if (lane < 4) {
                int cgn = bn + wn * 64 + nj * 8 + 2 * lane;
                if (cgn < Ncol) {
                    atomicAdd(&g_bnsum[cgn],     s0);
                    atomicAdd(&g_bnsum[cgn + 1], s1);
                    atomicAdd(&g_bnsq[cgn],      q0);
                    atomicAdd(&g_bnsq[cgn + 1],  q1);
                }
            }
        }
    }
}

// ---------------- weight transpose+round: [K,Ncol] -> tf32 K-major [Ncol,K] --
__global__ void wt_k(const float* __restrict__ src, float* __restrict__ dst,
                     int K, int Ncol) {
    __shared__ float t[32][33];
    int bx = blockIdx.x * 32, by = blockIdx.y * 32;
    int x = bx + threadIdx.x;     // n
#pragma unroll
    for (int j = 0; j < 32; j += 8) {
        int y = by + threadIdx.y + j;   // k
        if (x < Ncol && y < K) t[threadIdx.y + j][threadIdx.x] = src[(size_t)y * Ncol + x];
    }
    __syncthreads();
    int xk = by + threadIdx.x;    // k
#pragma unroll
    for (int j = 0; j < 32; j += 8) {
        int yn = bx + threadIdx.y + j;  // n
        if (xk < K && yn < Ncol)
            dst[(size_t)yn * K + xk] = tf32r(t[threadIdx.x][threadIdx.y + j]);
    }
}

// ---------------- node embed ----------------
__global__ void embed_k(const int* __restrict__ x,
                        const float* __restrict__ e1,
                        const float* __restrict__ e2) {
    long long i = (long long)blockIdx.x * blockDim.x + threadIdx.x;
    if (i >= (long long)NN * EMB) return;
    int r = (int)(i / EMB);
    int f = (int)(i - (long long)r * EMB);
    g_h[i] = e1[x[2 * r] * EMB + f] + e2[x[2 * r + 1] * EMB + f];
}

// ---------------- CSR build (once per call) ----------------
__global__ void deg_zero_k() {
    int i = blockIdx.x * blockDim.x + threadIdx.x;
    if (i < NN) g_deg[i] = 0;
    if (i < EMB) { g_bnsum[i] = 0.f; g_bnsq[i] = 0.f; }   // one-time BN zero
}
__global__ void deg_count_k(const int* __restrict__ ei) {
    int e = blockIdx.x * blockDim.x + threadIdx.x;
    if (e < EE) atomicAdd(&g_deg[ei[EE + e]], 1);
}
__global__ void scan1_k() {
    __shared__ int ssum[256];
    int tid = threadIdx.x;
    int base = blockIdx.x * 1024;
    int v[4]; int tot = 0;
#pragma unroll
    for (int i = 0; i < 4; i++) {
        int idx = base + tid * 4 + i;
        v[i] = (idx < NN) ? g_deg[idx] : 0;
        tot += v[i];
    }
    ssum[tid] = tot;
    __syncthreads();
    for (int off = 1; off < 256; off <<= 1) {
        int t = (tid >= off) ? ssum[tid - off] : 0;
        __syncthreads();
        ssum[tid] += t;
        __syncthreads();
    }
    int run = ssum[tid] - tot;
#pragma unroll
    for (int i = 0; i < 4; i++) {
        int idx = base + tid * 4 + i;
        if (idx < NN) g_off[idx] = run;
        run += v[i];
    }
    if (tid == 255) g_part[blockIdx.x] = ssum[255];
}
__global__ void scan2_k(int nb) {
    if (threadIdx.x == 0) {
        int run = 0;
        for (int b = 0; b < nb; b++) { int t = g_part[b]; g_part[b] = run; run += t; }
    }
}
__global__ void scan3_k() {
    int i = blockIdx.x * blockDim.x + threadIdx.x;
    if (i < NN) {
        int o = g_off[i] + g_part[i >> 10];
        g_off[i] = o;
        g_fill[i] = o;
    }
    if (i == 0) g_off[NN] = EE;
}
__global__ void fill_k(const int* __restrict__ ei, const int* __restrict__ ea) {
    int e = blockIdx.x * blockDim.x + threadIdx.x;
    if (e >= EE) return;
    int s = ei[e];
    int d = ei[EE + e];
    unsigned combo = (unsigned)(ea[2 * e] * 3 + ea[2 * e + 1]);
    int pos = atomicAdd(&g_fill[d], 1);
    g_edge[pos] = (unsigned)s | (combo << 17);
}

// ---------------- per-layer combo table ----------------
__global__ void ctab_k(const float* __restrict__ ee1l, const float* __restrict__ ee2l) {
    int i = blockIdx.x * blockDim.x + threadIdx.x;
    if (i >= 18 * EMB) return;
    int combo = i / EMB, f = i - combo * EMB;
    g_ctab[i] = ee1l[(combo / 3) * EMB + f] + ee2l[(combo % 3) * EMB + f];
}

// ---------------- gather: warp/node, BN+ReLU fused, tf32-rounded out --------
template <bool BN>
__global__ void __launch_bounds__(256)
gather_k() {
    __shared__ float4 sctab[18 * EMB / 4];
    __shared__ float4 ssc[EMB / 4 + 1];
    __shared__ float4 ssh[EMB / 4 + 1];
    int tid = threadIdx.x;
    const float4* gt = (const float4*)g_ctab;
    for (int i = tid; i < 18 * EMB / 4; i += 256) sctab[i] = gt[i];
    if (BN) {
        const float4* sc = (const float4*)g_bnscale;
        const float4* sh = (const float4*)g_bnshift;
        for (int i = tid; i < EMB / 4; i += 256) { ssc[i] = sc[i]; ssh[i] = sh[i]; }
    }
    __syncthreads();
    int node = blockIdx.x * 8 + (tid >> 5);
    if (node >= NN) return;
    int lane = tid & 31;
    int i0 = lane, i1 = lane + 32, i2 = lane + 64;
    float4 sc0, sc1, sc2, sh0, sh1, sh2;
    if (BN) {
        sc0 = ssc[i0]; sh0 = ssh[i0];
        sc1 = ssc[i1]; sh1 = ssh[i1];
        if (lane < 11) { sc2 = ssc[i2]; sh2 = ssh[i2]; }
    }
    auto norm = [&](float4 h, const float4& sc, const float4& sh) -> float4 {
        if (!BN) return h;
        return make_float4(fmaxf(fmaf(h.x, sc.x, sh.x), 0.f),
                           fmaxf(fmaf(h.y, sc.y, sh.y), 0.f),
                           fmaxf(fmaf(h.z, sc.z, sh.z), 0.f),
                           fmaxf(fmaf(h.w, sc.w, sh.w), 0.f));
    };
    float4 a0, a1, a2;
    {
        const float4* hn = (const float4*)(g_h + (size_t)node * EMB);
        const float4* self = &sctab[12 * 75];
        float4 h0 = norm(hn[i0], sc0, sh0), c0 = self[i0];
        float4 h1 = norm(hn[i1], sc1, sh1), c1 = self[i1];
        a0 = make_float4(h0.x + c0.x, h0.y + c0.y, h0.z + c0.z, h0.w + c0.w);
        a1 = make_float4(h1.x + c1.x, h1.y + c1.y, h1.z + c1.z, h1.w + c1.w);
        a2 = make_float4(0.f, 0.f, 0.f, 0.f);
        if (lane < 11) {
            float4 h2 = norm(hn[i2], sc2, sh2), c2 = self[i2];
            a2 = make_float4(h2.x + c2.x, h2.y + c2.y, h2.z + c2.z, h2.w + c2.w);
        }
    }
    int s = g_off[node], e = g_off[node + 1];
    int p = s;
    for (; p + 1 < e; p += 2) {
        unsigned pka = g_edge[p], pkb = g_edge[p + 1];
        const float4* ha = (const float4*)(g_h + (size_t)(pka & SRCMASK) * EMB);
        const float4* hb = (const float4*)(g_h + (size_t)(pkb & SRCMASK) * EMB);
        const float4* ca = &sctab[(pka >> 17) * 75];
        const float4* cb = &sctab[(pkb >> 17) * 75];
        float4 ha0 = ha[i0], hb0 = hb[i0];
        float4 ha1 = ha[i1], hb1 = hb[i1];
        float4 ha2, hb2;
        if (lane < 11) { ha2 = ha[i2]; hb2 = hb[i2]; }
        ha0 = norm(ha0, sc0, sh0); hb0 = norm(hb0, sc0, sh0);
        ha1 = norm(ha1, sc1, sh1); hb1 = norm(hb1, sc1, sh1);
        float4 c;
        c = ca[i0]; a0.x += ha0.x + c.x; a0.y += ha0.y + c.y; a0.z += ha0.z + c.z; a0.w += ha0.w + c.w;
        c = cb[i0]; a0.x += hb0.x + c.x; a0.y += hb0.y + c.y; a0.z += hb0.z + c.z; a0.w += hb0.w + c.w;
        c = ca[i1]; a1.x += ha1.x + c.x; a1.y += ha1.y + c.y; a1.z += ha1.z + c.z; a1.w += ha1.w + c.w;
        c = cb[i1]; a1.x += hb1.x + c.x; a1.y += hb1.y + c.y; a1.z += hb1.z + c.z; a1.w += hb1.w + c.w;
        if (lane < 11) {
            ha2 = norm(ha2, sc2, sh2); hb2 = norm(hb2, sc2, sh2);
            c = ca[i2]; a2.x += ha2.x + c.x; a2.y += ha2.y + c.y; a2.z += ha2.z + c.z; a2.w += ha2.w + c.w;
            c = cb[i2]; a2.x += hb2.x + c.x; a2.y += hb2.y + c.y; a2.z += hb2.z + c.z; a2.w += hb2.w + c.w;
        }
    }
    for (; p < e; p++) {
        unsigned pk = g_edge[p];
        const float4* hs = (const float4*)(g_h + (size_t)(pk & SRCMASK) * EMB);
        const float4* ct = &sctab[(pk >> 17) * 75];
        float4 h0 = norm(hs[i0], sc0, sh0), c0 = ct[i0];
        a0.x += h0.x + c0.x; a0.y += h0.y + c0.y; a0.z += h0.z + c0.z; a0.w += h0.w + c0.w;
        float4 h1 = norm(hs[i1], sc1, sh1), c1 = ct[i1];
        a1.x += h1.x + c1.x; a1.y += h1.y + c1.y; a1.z += h1.z + c1.z; a1.w += h1.w + c1.w;
        if (lane < 11) {
            float4 h2 = norm(hs[i2], sc2, sh2), c2 = ct[i2];
            a2.x += h2.x + c2.x; a2.y += h2.y + c2.y; a2.z += h2.z + c2.z; a2.w += h2.w + c2.w;
        }
    }
    auto rnd4 = [](float4 v) {
        return make_float4(tf32r(v.x), tf32r(v.y), tf32r(v.z), tf32r(v.w));
    };
    float4* ag = (float4*)(g_agg + (size_t)node * EMB);
    ag[i0] = rnd4(a0);
    ag[i1] = rnd4(a1);
    if (lane < 11) ag[i2] = rnd4(a2);
}

// ---------------- BatchNorm ----------------
// reads sums, computes scale/shift, and zeroes sums for the next layer
__global__ void bnfin_k(const float* __restrict__ gamma,
                        const float* __restrict__ beta) {
    int f = threadIdx.x;
    if (f >= EMB) return;
    float m   = g_bnsum[f] * (1.f / NN);
    float var = g_bnsq[f] * (1.f / NN) - m * m;
    float sc  = rsqrtf(var + EPSV) * gamma[f];
    g_bnscale[f] = sc;
    g_bnshift[f] = beta[f] - m * sc;
    g_bnsum[f] = 0.f;
    g_bnsq[f]  = 0.f;
}
__global__ void bn_apply_k() {
    long long i = (long long)blockIdx.x * blockDim.x + threadIdx.x;
    if (i >= (long long)NN * EMB) return;
    int f = (int)(i % EMB);
    g_h[i] = tf32r(fmaxf(fmaf(g_h[i], g_bnscale[f], g_bnshift[f]), 0.f));
}

// ---------------- pooling (mean of h per graph, BEFORE projection) ----------
__global__ void start_init_k() {
    int g = blockIdx.x * blockDim.x + threadIdx.x;
    if (g <= GG) g_start[g] = NN;
}
__global__ void bounds_k(const int* __restrict__ batch) {
    int r = blockIdx.x * blockDim.x + threadIdx.x;
    if (r >= NN) return;
    int b = batch[r];
    int pb = (r == 0) ? -1 : batch[r - 1];
    for (int g = pb + 1; g <= b; g++) g_start[g] = r;
}
__global__ void __launch_bounds__(320)
pool_hm_k() {
    int g = blockIdx.x, f = threadIdx.x;
    if (f >= EMB) return;
    int s = g_start[g], e = g_start[g + 1];
    float acc = 0.f;
    for (int r = s; r < e; r++) acc += g_h[(size_t)r * EMB + f];
    float c = fmaxf((float)(e - s), 1.f);
    g_hm[(size_t)g * EMB + f] = tf32r(acc / c);
}

// head: relu(pooled @ pw1 + pb1) @ pw2 + pb2 ; reads pooled from `out`
__global__ void __launch_bounds__(128)
pred_k(const float* __restrict__ pw1, const float* __restrict__ pb1,
       const float* __restrict__ pw2, const float* __restrict__ pb2,
       float* __restrict__ out) {
    __shared__ float sp[FEATD];
    __shared__ float sh[128];
    int g = blockIdx.x, t = threadIdx.x;
    sp[t]       = out[(size_t)g * FEATD + t];
    sp[t + 128] = out[(size_t)g * FEATD + t + 128];
    __syncthreads();
    float acc = pb1[t];
    for (int k = 0; k < FEATD; k++) acc = fmaf(sp[k], pw1[k * 128 + t], acc);
    sh[t] = fmaxf(acc, 0.f);
    __syncthreads();
    if (t < 2) {
        float a = pb2[t];
        for (int k = 0; k < 128; k++) a = fmaf(sh[k], pw2[k * 2 + t], a);
        out[(size_t)GG * FEATD + g * 2 + t] = a;
    }
}

// ---------------- launch ----------------
extern "C" void kernel_launch(void* const* d_in, const int* in_sizes, int n_in,
                              void* d_out, int out_size) {
    const int*   x     = (const int*)d_in[0];
    const int*   ei    = (const int*)d_in[1];
    const int*   ea    = (const int*)d_in[2];
    const int*   batch = (const int*)d_in[3];
    const float* xemb1 = (const float*)d_in[4];
    const float* xemb2 = (const float*)d_in[5];
    const float* ee1   = (const float*)d_in[6];
    const float* ee2   = (const float*)d_in[7];
    const float* w1    = (const float*)d_in[8];
    const float* b1    = (const float*)d_in[9];
    const float* w2    = (const float*)d_in[10];
    const float* b2    = (const float*)d_in[11];
    const float* gamma = (const float*)d_in[12];
    const float* beta  = (const float*)d_in[13];
    const float* fw    = (const float*)d_in[14];
    const float* fb    = (const float*)d_in[15];
    const float* pw1   = (const float*)d_in[16];
    const float* pb1   = (const float*)d_in[17];
    const float* pw2   = (const float*)d_in[18];
    const float* pb2   = (const float*)d_in[19];
    float* out = (float*)d_out;

    float *p_h, *p_agg, *p_hidden, *p_hm, *p_w1t, *p_w2t, *p_fwt;
    cudaGetSymbolAddress((void**)&p_h, g_h);
    cudaGetSymbolAddress((void**)&p_agg, g_agg);
    cudaGetSymbolAddress((void**)&p_hidden, g_hidden);
    cudaGetSymbolAddress((void**)&p_hm, g_hm);
    cudaGetSymbolAddress((void**)&p_w1t, g_w1t);
    cudaGetSymbolAddress((void**)&p_w2t, g_w2t);
    cudaGetSymbolAddress((void**)&p_fwt, g_fwt);

    const long long nelem = (long long)NN * EMB;
    const int T = 256;
    const int gNE = (int)((nelem + T - 1) / T);
    const int MB = (NN + 127) / 128;
    const int NB_SCAN = (NN + 1023) / 1024;
    dim3 tb(32, 8);

    embed_k<<<gNE, T>>>(x, xemb1, xemb2);

    // CSR build + one-time BN zero
    deg_zero_k<<<(NN + T - 1) / T, T>>>();
    deg_count_k<<<(EE + T - 1) / T, T>>>(ei);
    scan1_k<<<NB_SCAN, 256>>>();
    scan2_k<<<1, 32>>>(NB_SCAN);
    scan3_k<<<(NN + T - 1) / T, T>>>();
    fill_k<<<(EE + T - 1) / T, T>>>(ei, ea);

    // graph bounds (independent; hoisted)
    start_init_k<<<(GG + 1 + T - 1) / T, T>>>();
    bounds_k<<<(NN + T - 1) / T, T>>>(batch);

    // all weight transposes up front (weights constant within a call)
    for (int l = 0; l < LL; l++) {
        wt_k<<<dim3((H2 + 31) / 32, (EMB + 31) / 32), tb>>>(
            w1 + (size_t)l * EMB * H2, p_w1t + (size_t)l * H2 * EMB, EMB, H2);
        wt_k<<<dim3((EMB + 31) / 32, (H2 + 31) / 32), tb>>>(
            w2 + (size_t)l * H2 * EMB, p_w2t + (size_t)l * EMB * H2, H2, EMB);
    }
    wt_k<<<dim3((FEATD + 31) / 32, (EMB + 31) / 32), tb>>>(fw, p_fwt, EMB, FEATD);

    for (int l = 0; l < LL; l++) {
        const float* ee1l = ee1 + (size_t)l * 6 * EMB;
        const float* ee2l = ee2 + (size_t)l * 3 * EMB;
        ctab_k<<<(18 * EMB + T - 1) / T, T>>>(ee1l, ee2l);
        if (l == 0) gather_k<false><<<(NN + 7) / 8, 256>>>();
        else        gather_k<true><<<(NN + 7) / 8, 256>>>();

        mgemm_k<true, true, false><<<dim3((H2 + 127) / 128, MB), 128>>>(
            p_agg, p_w1t + (size_t)l * H2 * EMB, b1 + (size_t)l * H2,
            p_hidden, NN, EMB, H2);
        mgemm_k<false, false, true><<<dim3((EMB + 127) / 128, MB), 128>>>(
            p_hidden, p_w2t + (size_t)l * EMB * H2, b2 + (size_t)l * EMB,
            p_h, NN, H2, EMB);

        bnfin_k<<<1, 320>>>(gamma + (size_t)l * EMB, beta + (size_t)l * EMB);
    }

    bn_apply_k<<<gNE, T>>>();

    // pool BEFORE projection: pooled = mean(h) @ fw + fb  (linearity)
    pool_hm_k<<<GG, 320>>>();
    mgemm_k<false, false, false><<<dim3((FEATD + 127) / 128, (GG + 127) / 128), 128>>>(
        p_hm, p_fwt, fb, out, GG, EMB, FEATD);

    pred_k<<<GG, 128>>>(pw1, pb1, pw2, pb2, out);
}

// round 16
// speedup vs baseline: 1.2368x; 1.0058x over previous
#include <cuda_runtime.h>
#include <cuda_bf16.h>
#include <cuda_pipeline_primitives.h>
#include <cstdio>
#include <cstdint>

#define NN 100000
#define EE 500000
#define GG 2000
#define LL 5
#define EMB 300
#define H2  600
#define FEATD 256
#define EPSV 1e-5f
#define SRCMASK 0x1FFFF

// ---------------- scratch (device globals; no allocs allowed) ----------------
__device__ float g_h[(size_t)NN * EMB];
__device__ float g_agg[(size_t)NN * EMB];
__device__ float g_hidden[(size_t)NN * H2];
__device__ float g_hm[(size_t)GG * EMB];        // per-graph mean of h
__device__ float g_bnsum[EMB];
__device__ float g_bnsq[EMB];
__device__ float g_bnscale[EMB];
__device__ float g_bnshift[EMB];
__device__ float g_ctab[18 * EMB];
__device__ float g_w1t[(size_t)LL * H2 * EMB];  // transposed tf32 weights
__device__ float g_w2t[(size_t)LL * EMB * H2];
__device__ float g_fwt[(size_t)FEATD * EMB];
// CSR scratch
__device__ int g_deg[NN];
__device__ int g_off[NN + 1];
__device__ int g_fill[NN];
__device__ unsigned g_edge[EE];
__device__ int g_part[128];
__device__ int g_start[GG + 1];

// ---------------- helpers ----------------
__device__ __forceinline__ float tf32r(float x) {
    float y;
    asm("cvt.rna.tf32.f32 %0, %1;" : "=f"(y) : "f"(x));
    return y;
}
__device__ __forceinline__ uint32_t smem_u32(const void* p) {
    uint32_t a;
    asm("{ .reg .u64 t; cvta.to.shared.u64 t, %1; cvt.u32.u64 %0, t; }"
        : "=r"(a) : "l"(p));
    return a;
}
#define LDSM4(r, addr) \
    asm volatile("ldmatrix.sync.aligned.m8n8.x4.shared.b16 {%0,%1,%2,%3}, [%4];" \
                 : "=r"((r)[0]), "=r"((r)[1]), "=r"((r)[2]), "=r"((r)[3]) \
                 : "r"(addr))
#define MMA_TF32(d, a, b0, b1) \
    asm volatile("mma.sync.aligned.m16n8k8.row.col.f32.tf32.tf32.f32 " \
                 "{%0,%1,%2,%3}, {%4,%5,%6,%7}, {%8,%9}, {%0,%1,%2,%3};" \
                 : "+f"((d)[0]), "+f"((d)[1]), "+f"((d)[2]), "+f"((d)[3]) \
                 : "r"((a)[0]), "r"((a)[1]), "r"((a)[2]), "r"((a)[3]), \
                   "r"(b0), "r"(b1))

// ======== tf32 mma GEMM: C[M,Ncol] = act(A[M,K] @ Bt[Ncol,K]^T + bias)
// Bt is K-major [Ncol,K] (tf32-rounded). BM=128 BN=128 BK=16, 128 thr,
// 4 warps as 2(M) x 2(N), warp tile 64x64.
#define ALD 20
#define STG_FLT (128 * ALD)

template <bool RELU, bool ROUND_OUT, bool STATS>
__global__ void __launch_bounds__(128)
mgemm_k(const float* __restrict__ A, const float* __restrict__ Bt,
        const float* __restrict__ bias, float* __restrict__ C,
        int M, int K, int Ncol) {
    __shared__ __align__(16) float sA[2 * STG_FLT];
    __shared__ __align__(16) float sB[2 * STG_FLT];

    const int tid = threadIdx.x;
    const int warp = tid >> 5;
    const int lane = tid & 31;
    const int wm = warp & 1;
    const int wn = warp >> 1;
    const int bm = blockIdx.y * 128;
    const int bn = blockIdx.x * 128;

    const uint32_t sA_u = smem_u32(sA);
    const uint32_t sB_u = smem_u32(sB);

    uint32_t aoff[4], boff[4];
#pragma unroll
    for (int mi = 0; mi < 4; mi++) {
        int row = wm * 64 + mi * 16 + (lane & 15);
        int col = (lane >> 4) * 4;
        aoff[mi] = (uint32_t)((row * ALD + col) * 4);
    }
#pragma unroll
    for (int pj = 0; pj < 4; pj++) {
        int nrow = wn * 64 + pj * 16 + (lane & 7) + ((lane >> 4) << 3);
        int col  = ((lane >> 3) & 1) * 4;
        boff[pj] = (uint32_t)((nrow * ALD + col) * 4);
    }

    float acc[4][8][4];
#pragma unroll
    for (int i = 0; i < 4; i++)
#pragma unroll
        for (int j = 0; j < 8; j++)
#pragma unroll
            for (int e = 0; e < 4; e++) acc[i][j][e] = 0.f;

    const int KT = (K + 15) / 16;

    auto load_tiles = [&](int s, int k0) {
#pragma unroll
        for (int i = 0; i < 4; i++) {
            int t = tid + i * 128;
            int row = t >> 2, q = t & 3;
            int gk = k0 + q * 4;
            {
                int gm = bm + row; if (gm >= M) gm = M - 1;
                float* dst = &sA[s * STG_FLT + row * ALD + q * 4];
                if (gk < K)
                    __pipeline_memcpy_async(dst, &A[(size_t)gm * K + gk], 16);
                else { dst[0] = 0.f; dst[1] = 0.f; dst[2] = 0.f; dst[3] = 0.f; }
            }
            {
                int gn = bn + row; if (gn >= Ncol) gn = Ncol - 1;
                float* dst = &sB[s * STG_FLT + row * ALD + q * 4];
                if (gk < K)
                    __pipeline_memcpy_async(dst, &Bt[(size_t)gn * K + gk], 16);
                else { dst[0] = 0.f; dst[1] = 0.f; dst[2] = 0.f; dst[3] = 0.f; }
            }
        }
    };

    load_tiles(0, 0);
    __pipeline_commit();

    for (int kt = 0; kt < KT; kt++) {
        int s = kt & 1;
        bool has_next = (kt + 1 < KT);
        if (has_next) { load_tiles(s ^ 1, (kt + 1) * 16); __pipeline_commit(); }
        __pipeline_wait_prior(has_next ? 1 : 0);
        __syncthreads();

        uint32_t baseA = sA_u + s * (STG_FLT * 4);
        uint32_t baseB = sB_u + s * (STG_FLT * 4);
#pragma unroll
        for (int kk8 = 0; kk8 < 2; kk8++) {
            uint32_t a[4][4], b[4][4];
#pragma unroll
            for (int mi = 0; mi < 4; mi++)
                LDSM4(a[mi], baseA + aoff[mi] + kk8 * 32);
#pragma unroll
            for (int pj = 0; pj < 4; pj++)
                LDSM4(b[pj], baseB + boff[pj] + kk8 * 32);
#pragma unroll
            for (int mi = 0; mi < 4; mi++)
#pragma unroll
                for (int pj = 0; pj < 4; pj++) {
                    MMA_TF32(acc[mi][2 * pj],     a[mi], b[pj][0], b[pj][1]);
                    MMA_TF32(acc[mi][2 * pj + 1], a[mi], b[pj][2], b[pj][3]);
                }
        }
        __syncthreads();
    }

    const int qr = lane >> 2;
    const int qc = 2 * (lane & 3);
#pragma unroll
    for (int nj = 0; nj < 8; nj++) {
        int gn = bn + wn * 64 + nj * 8 + qc;
        float s0 = 0.f, s1 = 0.f, q0 = 0.f, q1 = 0.f;
        if (gn < Ncol) {
            float2 bb = *(const float2*)&bias[gn];
#pragma unroll
            for (int mi = 0; mi < 4; mi++) {
                int gm0 = bm + wm * 64 + mi * 16 + qr;
                int gm1 = gm0 + 8;
                float* d = acc[mi][nj];
                if (gm0 < M) {
                    float v0 = d[0] + bb.x, v1 = d[1] + bb.y;
                    if (RELU) { v0 = fmaxf(v0, 0.f); v1 = fmaxf(v1, 0.f); }
                    if (STATS) { s0 += v0; s1 += v1; q0 += v0 * v0; q1 += v1 * v1; }
                    if (ROUND_OUT) { v0 = tf32r(v0); v1 = tf32r(v1); }
                    *(float2*)&C[(size_t)gm0 * Ncol + gn] = make_float2(v0, v1);
                }
                if (gm1 < M) {
                    float v2 = d[2] + bb.x, v3 = d[3] + bb.y;
                    if (RELU) { v2 = fmaxf(v2, 0.f); v3 = fmaxf(v3, 0.f); }
                    if (STATS) { s0 += v2; s1 += v3; q0 += v2 * v2; q1 += v3 * v3; }
                    if (ROUND_OUT) { v2 = tf32r(v2); v3 = tf32r(v3); }
                    *(float2*)&C[(size_t)gm1 * Ncol + gn] = make_float2(v2, v3);
                }
            }
        }
        if (STATS) {
#pragma unroll
            for (int off = 4; off < 32; off <<= 1) {
                s0 += __shfl_xor_sync(0xFFFFFFFF, s0, off);
                s1 += __shfl_xor_sync(0xFFFFFFFF, s1, off);
                q0 += __shfl_xor_sync(0xFFFFFFFF, q0, off);
                q1 += __shfl_xor_sync(0xFFFFFFFF, q1, off);
            }
            if (lane < 4) {
                int cgn = bn + wn * 64 + nj * 8 + 2 * lane;
                if (cgn < Ncol) {
                    atomicAdd(&g_bnsum[cgn],     s0);
                    atomicAdd(&g_bnsum[cgn + 1], s1);
                    atomicAdd(&g_bnsq[cgn],      q0);
                    atomicAdd(&g_bnsq[cgn + 1],  q1);
                }
            }
        }
    }
}

// ---------------- weight transpose+round: [K,Ncol] -> tf32 K-major [Ncol,K] --
__global__ void wt_k(const float* __restrict__ src, float* __restrict__ dst,
                     int K, int Ncol) {
    __shared__ float t[32][33];
    int bx = blockIdx.x * 32, by = blockIdx.y * 32;
    int x = bx + threadIdx.x;     // n
#pragma unroll
    for (int j = 0; j < 32; j += 8) {
        int y = by + threadIdx.y + j;   // k
        if (x < Ncol && y < K) t[threadIdx.y + j][threadIdx.x] = src[(size_t)y * Ncol + x];
    }
    __syncthreads();
    int xk = by + threadIdx.x;    // k
#pragma unroll
    for (int j = 0; j < 32; j += 8) {
        int yn = bx + threadIdx.y + j;  // n
        if (xk < K && yn < Ncol)
            dst[(size_t)yn * K + xk] = tf32r(t[threadIdx.x][threadIdx.y + j]);
    }
}

// ---------------- node embed ----------------
__global__ void embed_k(const int* __restrict__ x,
                        const float* __restrict__ e1,
                        const float* __restrict__ e2) {
    long long i = (long long)blockIdx.x * blockDim.x + threadIdx.x;
    if (i >= (long long)NN * EMB) return;
    int r = (int)(i / EMB);
    int f = (int)(i - (long long)r * EMB);
    g_h[i] = e1[x[2 * r] * EMB + f] + e2[x[2 * r + 1] * EMB + f];
}

// ---------------- CSR build (once per call) ----------------
__global__ void deg_zero_k() {
    int i = blockIdx.x * blockDim.x + threadIdx.x;
    if (i < NN) g_deg[i] = 0;
    if (i < EMB) { g_bnsum[i] = 0.f; g_bnsq[i] = 0.f; }
}
__global__ void deg_count_k(const int* __restrict__ ei) {
    int e = blockIdx.x * blockDim.x + threadIdx.x;
    if (e < EE) atomicAdd(&g_deg[ei[EE + e]], 1);
}
__global__ void scan1_k() {
    __shared__ int ssum[256];
    int tid = threadIdx.x;
    int base = blockIdx.x * 1024;
    int v[4]; int tot = 0;
#pragma unroll
    for (int i = 0; i < 4; i++) {
        int idx = base + tid * 4 + i;
        v[i] = (idx < NN) ? g_deg[idx] : 0;
        tot += v[i];
    }
    ssum[tid] = tot;
    __syncthreads();
    for (int off = 1; off < 256; off <<= 1) {
        int t = (tid >= off) ? ssum[tid - off] : 0;
        __syncthreads();
        ssum[tid] += t;
        __syncthreads();
    }
    int run = ssum[tid] - tot;
#pragma unroll
    for (int i = 0; i < 4; i++) {
        int idx = base + tid * 4 + i;
        if (idx < NN) g_off[idx] = run;
        run += v[i];
    }
    if (tid == 255) g_part[blockIdx.x] = ssum[255];
}
__global__ void scan2_k(int nb) {
    if (threadIdx.x == 0) {
        int run = 0;
        for (int b = 0; b < nb; b++) { int t = g_part[b]; g_part[b] = run; run += t; }
    }
}
__global__ void scan3_k() {
    int i = blockIdx.x * blockDim.x + threadIdx.x;
    if (i < NN) {
        int o = g_off[i] + g_part[i >> 10];
        g_off[i] = o;
        g_fill[i] = o;
    }
    if (i == 0) g_off[NN] = EE;
}
__global__ void fill_k(const int* __restrict__ ei, const int* __restrict__ ea) {
    int e = blockIdx.x * blockDim.x + threadIdx.x;
    if (e >= EE) return;
    int s = ei[e];
    int d = ei[EE + e];
    unsigned combo = (unsigned)(ea[2 * e] * 3 + ea[2 * e + 1]);
    int pos = atomicAdd(&g_fill[d], 1);
    g_edge[pos] = (unsigned)s | (combo << 17);
}

// ---------------- per-layer combo table ----------------
__global__ void ctab_k(const float* __restrict__ ee1l, const float* __restrict__ ee2l) {
    int i = blockIdx.x * blockDim.x + threadIdx.x;
    if (i >= 18 * EMB) return;
    int combo = i / EMB, f = i - combo * EMB;
    g_ctab[i] = ee1l[(combo / 3) * EMB + f] + ee2l[(combo % 3) * EMB + f];
}

// ---------------- gather: warp/node, BN+ReLU fused, 4-edge unroll -----------
template <bool BN>
__global__ void __launch_bounds__(256)
gather_k() {
    __shared__ float4 sctab[18 * EMB / 4];
    __shared__ float4 ssc[EMB / 4 + 1];
    __shared__ float4 ssh[EMB / 4 + 1];
    int tid = threadIdx.x;
    const float4* gt = (const float4*)g_ctab;
    for (int i = tid; i < 18 * EMB / 4; i += 256) sctab[i] = gt[i];
    if (BN) {
        const float4* sc = (const float4*)g_bnscale;
        const float4* sh = (const float4*)g_bnshift;
        for (int i = tid; i < EMB / 4; i += 256) { ssc[i] = sc[i]; ssh[i] = sh[i]; }
    }
    __syncthreads();
    int node = blockIdx.x * 8 + (tid >> 5);
    if (node >= NN) return;
    int lane = tid & 31;
    int i0 = lane, i1 = lane + 32, i2 = lane + 64;   // i2 valid iff lane<11
    const bool has2 = (lane < 11);
    float4 sc0, sc1, sc2, sh0, sh1, sh2;
    if (BN) {
        sc0 = ssc[i0]; sh0 = ssh[i0];
        sc1 = ssc[i1]; sh1 = ssh[i1];
        if (has2) { sc2 = ssc[i2]; sh2 = ssh[i2]; }
    }
    auto norm = [&](float4 h, const float4& sc, const float4& sh) -> float4 {
        if (!BN) return h;
        return make_float4(fmaxf(fmaf(h.x, sc.x, sh.x), 0.f),
                           fmaxf(fmaf(h.y, sc.y, sh.y), 0.f),
                           fmaxf(fmaf(h.z, sc.z, sh.z), 0.f),
                           fmaxf(fmaf(h.w, sc.w, sh.w), 0.f));
    };
    auto add4 = [](float4& a, const float4& h, const float4& c) {
        a.x += h.x + c.x; a.y += h.y + c.y; a.z += h.z + c.z; a.w += h.w + c.w;
    };
    float4 a0, a1, a2;
    {
        const float4* hn = (const float4*)(g_h + (size_t)node * EMB);
        const float4* self = &sctab[12 * 75];
        float4 h0 = norm(hn[i0], sc0, sh0), c0 = self[i0];
        float4 h1 = norm(hn[i1], sc1, sh1), c1 = self[i1];
        a0 = make_float4(h0.x + c0.x, h0.y + c0.y, h0.z + c0.z, h0.w + c0.w);
        a1 = make_float4(h1.x + c1.x, h1.y + c1.y, h1.z + c1.z, h1.w + c1.w);
        a2 = make_float4(0.f, 0.f, 0.f, 0.f);
        if (has2) {
            float4 h2 = norm(hn[i2], sc2, sh2), c2 = self[i2];
            a2 = make_float4(h2.x + c2.x, h2.y + c2.y, h2.z + c2.z, h2.w + c2.w);
        }
    }
    int s = g_off[node], e = g_off[node + 1];
    int p = s;
    // 4-edge unroll: up to 12 independent gathers in flight
    for (; p + 3 < e; p += 4) {
        unsigned pk[4];
        const float4* hp[4];
        const float4* cp[4];
#pragma unroll
        for (int u = 0; u < 4; u++) {
            pk[u] = g_edge[p + u];
            hp[u] = (const float4*)(g_h + (size_t)(pk[u] & SRCMASK) * EMB);
            cp[u] = &sctab[(pk[u] >> 17) * 75];
        }
        float4 h0[4], h1[4], h2[4];
#pragma unroll
        for (int u = 0; u < 4; u++) { h0[u] = hp[u][i0]; h1[u] = hp[u][i1]; }
        if (has2) {
#pragma unroll
            for (int u = 0; u < 4; u++) h2[u] = hp[u][i2];
        }
#pragma unroll
        for (int u = 0; u < 4; u++) {
            add4(a0, norm(h0[u], sc0, sh0), cp[u][i0]);
            add4(a1, norm(h1[u], sc1, sh1), cp[u][i1]);
        }
        if (has2) {
#pragma unroll
            for (int u = 0; u < 4; u++)
                add4(a2, norm(h2[u], sc2, sh2), cp[u][i2]);
        }
    }
    for (; p < e; p++) {
        unsigned pk = g_edge[p];
        const float4* hs = (const float4*)(g_h + (size_t)(pk & SRCMASK) * EMB);
        const float4* ct = &sctab[(pk >> 17) * 75];
        add4(a0, norm(hs[i0], sc0, sh0), ct[i0]);
        add4(a1, norm(hs[i1], sc1, sh1), ct[i1]);
        if (has2) add4(a2, norm(hs[i2], sc2, sh2), ct[i2]);
    }
    auto rnd4 = [](float4 v) {
        return make_float4(tf32r(v.x), tf32r(v.y), tf32r(v.z), tf32r(v.w));
    };
    float4* ag = (float4*)(g_agg + (size_t)node * EMB);
    ag[i0] = rnd4(a0);
    ag[i1] = rnd4(a1);
    if (has2) ag[i2] = rnd4(a2);
}

// ---------------- BatchNorm ----------------
__global__ void bnfin_k(const float* __restrict__ gamma,
                        const float* __restrict__ beta) {
    int f = threadIdx.x;
    if (f >= EMB) return;
    float m   = g_bnsum[f] * (1.f / NN);
    float var = g_bnsq[f] * (1.f / NN) - m * m;
    float sc  = rsqrtf(var + EPSV) * gamma[f];
    g_bnscale[f] = sc;
    g_bnshift[f] = beta[f] - m * sc;
    g_bnsum[f] = 0.f;
    g_bnsq[f]  = 0.f;
}

// ---------------- pooling (BN+ReLU fused on read; mean of h per graph) ------
__global__ void start_init_k() {
    int g = blockIdx.x * blockDim.x + threadIdx.x;
    if (g <= GG) g_start[g] = NN;
}
__global__ void bounds_k(const int* __restrict__ batch) {
    int r = blockIdx.x * blockDim.x + threadIdx.x;
    if (r >= NN) return;
    int b = batch[r];
    int pb = (r == 0) ? -1 : batch[r - 1];
    for (int g = pb + 1; g <= b; g++) g_start[g] = r;
}
__global__ void __launch_bounds__(320)
pool_hm_k() {
    int g = blockIdx.x, f = threadIdx.x;
    if (f >= EMB) return;
    float sc = g_bnscale[f], sh = g_bnshift[f];
    int s = g_start[g], e = g_start[g + 1];
    float acc = 0.f;
    for (int r = s; r < e; r++)
        acc += fmaxf(fmaf(g_h[(size_t)r * EMB + f], sc, sh), 0.f);
    float c = fmaxf((float)(e - s), 1.f);
    g_hm[(size_t)g * EMB + f] = tf32r(acc / c);
}

// head: relu(pooled @ pw1 + pb1) @ pw2 + pb2 ; reads pooled from `out`
__global__ void __launch_bounds__(128)
pred_k(const float* __restrict__ pw1, const float* __restrict__ pb1,
       const float* __restrict__ pw2, const float* __restrict__ pb2,
       float* __restrict__ out) {
    __shared__ float sp[FEATD];
    __shared__ float sh[128];
    int g = blockIdx.x, t = threadIdx.x;
    sp[t]       = out[(size_t)g * FEATD + t];
    sp[t + 128] = out[(size_t)g * FEATD + t + 128];
    __syncthreads();
    float acc = pb1[t];
    for (int k = 0; k < FEATD; k++) acc = fmaf(sp[k], pw1[k * 128 + t], acc);
    sh[t] = fmaxf(acc, 0.f);
    __syncthreads();
    if (t < 2) {
        float a = pb2[t];
        for (int k = 0; k < 128; k++) a = fmaf(sh[k], pw2[k * 2 + t], a);
        out[(size_t)GG * FEATD + g * 2 + t] = a;
    }
}

// ---------------- launch ----------------
extern "C" void kernel_launch(void* const* d_in, const int* in_sizes, int n_in,
                              void* d_out, int out_size) {
    const int*   x     = (const int*)d_in[0];
    const int*   ei    = (const int*)d_in[1];
    const int*   ea    = (const int*)d_in[2];
    const int*   batch = (const int*)d_in[3];
    const float* xemb1 = (const float*)d_in[4];
    const float* xemb2 = (const float*)d_in[5];
    const float* ee1   = (const float*)d_in[6];
    const float* ee2   = (const float*)d_in[7];
    const float* w1    = (const float*)d_in[8];
    const float* b1    = (const float*)d_in[9];
    const float* w2    = (const float*)d_in[10];
    const float* b2    = (const float*)d_in[11];
    const float* gamma = (const float*)d_in[12];
    const float* beta  = (const float*)d_in[13];
    const float* fw    = (const float*)d_in[14];
    const float* fb    = (const float*)d_in[15];
    const float* pw1   = (const float*)d_in[16];
    const float* pb1   = (const float*)d_in[17];
    const float* pw2   = (const float*)d_in[18];
    const float* pb2   = (const float*)d_in[19];
    float* out = (float*)d_out;

    float *p_h, *p_agg, *p_hidden, *p_hm, *p_w1t, *p_w2t, *p_fwt;
    cudaGetSymbolAddress((void**)&p_h, g_h);
    cudaGetSymbolAddress((void**)&p_agg, g_agg);
    cudaGetSymbolAddress((void**)&p_hidden, g_hidden);
    cudaGetSymbolAddress((void**)&p_hm, g_hm);
    cudaGetSymbolAddress((void**)&p_w1t, g_w1t);
    cudaGetSymbolAddress((void**)&p_w2t, g_w2t);
    cudaGetSymbolAddress((void**)&p_fwt, g_fwt);

    const long long nelem = (long long)NN * EMB;
    const int T = 256;
    const int gNE = (int)((nelem + T - 1) / T);
    const int MB = (NN + 127) / 128;
    const int NB_SCAN = (NN + 1023) / 1024;
    dim3 tb(32, 8);

    embed_k<<<gNE, T>>>(x, xemb1, xemb2);

    // CSR build + one-time BN zero
    deg_zero_k<<<(NN + T - 1) / T, T>>>();
    deg_count_k<<<(EE + T - 1) / T, T>>>(ei);
    scan1_k<<<NB_SCAN, 256>>>();
    scan2_k<<<1, 32>>>(NB_SCAN);
    scan3_k<<<(NN + T - 1) / T, T>>>();
    fill_k<<<(EE + T - 1) / T, T>>>(ei, ea);

    // graph bounds (independent; hoisted)
    start_init_k<<<(GG + 1 + T - 1) / T, T>>>();
    bounds_k<<<(NN + T - 1) / T, T>>>(batch);

    // all weight transposes up front
    for (int l = 0; l < LL; l++) {
        wt_k<<<dim3((H2 + 31) / 32, (EMB + 31) / 32), tb>>>(
            w1 + (size_t)l * EMB * H2, p_w1t + (size_t)l * H2 * EMB, EMB, H2);
        wt_k<<<dim3((EMB + 31) / 32, (H2 + 31) / 32), tb>>>(
            w2 + (size_t)l * H2 * EMB, p_w2t + (size_t)l * EMB * H2, H2, EMB);
    }
    wt_k<<<dim3((FEATD + 31) / 32, (EMB + 31) / 32), tb>>>(fw, p_fwt, EMB, FEATD);

    for (int l = 0; l < LL; l++) {
        const float* ee1l = ee1 + (size_t)l * 6 * EMB;
        const float* ee2l = ee2 + (size_t)l * 3 * EMB;
        ctab_k<<<(18 * EMB + T - 1) / T, T>>>(ee1l, ee2l);
        if (l == 0) gather_k<false><<<(NN + 7) / 8, 256>>>();
        else        gather_k<true><<<(NN + 7) / 8, 256>>>();

        mgemm_k<true, true, false><<<dim3((H2 + 127) / 128, MB), 128>>>(
            p_agg, p_w1t + (size_t)l * H2 * EMB, b1 + (size_t)l * H2,
            p_hidden, NN, EMB, H2);
        mgemm_k<false, false, true><<<dim3((EMB + 127) / 128, MB), 128>>>(
            p_hidden, p_w2t + (size_t)l * EMB * H2, b2 + (size_t)l * EMB,
            p_h, NN, H2, EMB);

        bnfin_k<<<1, 320>>>(gamma + (size_t)l * EMB, beta + (size_t)l * EMB);
    }

    // pool with final BN+ReLU fused; then pooled = mean @ fw + fb (linearity)
    pool_hm_k<<<GG, 320>>>();
    mgemm_k<false, false, false><<<dim3((FEATD + 127) / 128, (GG + 127) / 128), 128>>>(
        p_hm, p_fwt, fb, out, GG, EMB, FEATD);

    pred_k<<<GG, 128>>>(pw1, pb1, pw2, pb2, out);
}

// round 17
// speedup vs baseline: 1.5936x; 1.2884x over previous
#include <cuda_runtime.h>
#include <cuda_bf16.h>
#include <cuda_pipeline_primitives.h>
#include <cstdio>
#include <cstdint>

#define NN 100000
#define EE 500000
#define GG 2000
#define LL 5
#define EMB 300
#define H2  600
#define FEATD 256
#define EPSV 1e-5f
#define SRCMASK 0x1FFFF

// ---------------- scratch (device globals; no allocs allowed) ----------------
__device__ float g_h[(size_t)NN * EMB];
__device__ float g_agg[(size_t)NN * EMB];
__device__ float g_hidden[(size_t)NN * H2];
__device__ float g_hm[(size_t)GG * EMB];        // per-graph mean of h
__device__ float g_bnsum[EMB];
__device__ float g_bnsq[EMB];
__device__ float g_bnscale[EMB];
__device__ float g_bnshift[EMB];
__device__ float g_ctab[18 * EMB];
__device__ float g_w1t[(size_t)LL * H2 * EMB];  // transposed tf32 weights
__device__ float g_w2t[(size_t)LL * EMB * H2];
__device__ float g_fwt[(size_t)FEATD * EMB];
// CSR scratch
__device__ int g_deg[NN];
__device__ int g_off[NN + 1];
__device__ int g_fill[NN];
__device__ unsigned g_edge[EE];
__device__ int g_part[128];
__device__ int g_start[GG + 1];

// ---------------- helpers ----------------
__device__ __forceinline__ float tf32r(float x) {
    float y;
    asm("cvt.rna.tf32.f32 %0, %1;" : "=f"(y) : "f"(x));
    return y;
}
__device__ __forceinline__ uint32_t smem_u32(const void* p) {
    uint32_t a;
    asm("{ .reg .u64 t; cvta.to.shared.u64 t, %1; cvt.u32.u64 %0, t; }"
        : "=r"(a) : "l"(p));
    return a;
}
#define LDSM4(r, addr) \
    asm volatile("ldmatrix.sync.aligned.m8n8.x4.shared.b16 {%0,%1,%2,%3}, [%4];" \
                 : "=r"((r)[0]), "=r"((r)[1]), "=r"((r)[2]), "=r"((r)[3]) \
                 : "r"(addr))
#define MMA_TF32(d, a, b0, b1) \
    asm volatile("mma.sync.aligned.m16n8k8.row.col.f32.tf32.tf32.f32 " \
                 "{%0,%1,%2,%3}, {%4,%5,%6,%7}, {%8,%9}, {%0,%1,%2,%3};" \
                 : "+f"((d)[0]), "+f"((d)[1]), "+f"((d)[2]), "+f"((d)[3]) \
                 : "r"((a)[0]), "r"((a)[1]), "r"((a)[2]), "r"((a)[3]), \
                   "r"(b0), "r"(b1))

// ======== tf32 mma GEMM: C[M,Ncol] = act(A[M,K] @ Bt[Ncol,K]^T + bias)
// Bt is K-major [Ncol,K] (tf32-rounded). BK=16, 128 threads.
// Template geometry: NWC warp-columns (1 or 2), NWR = 4/NWC warp-rows,
// warp tile = (MI*16) x 64; BM = NWR*MI*16, BN = NWC*64.
//   <MI=4,NWC=2>: BM=128, BN=128  (GEMM1 / feat)
//   <MI=3,NWC=1>: BM=192, BN=64   (GEMM2: Ncol=300 -> 5 tiles, 6% waste)
#define ALD 20

template <bool RELU, bool ROUND_OUT, bool STATS, int MI, int NWC>
__global__ void __launch_bounds__(128)
mgemm_k(const float* __restrict__ A, const float* __restrict__ Bt,
        const float* __restrict__ bias, float* __restrict__ C,
        int M, int K, int Ncol) {
    constexpr int NWR = 4 / NWC;
    constexpr int BM = NWR * MI * 16;
    constexpr int BN = NWC * 64;
    constexpr int ASTG = BM * ALD;
    constexpr int BSTG = BN * ALD;
    __shared__ __align__(16) float sA[2 * ASTG];
    __shared__ __align__(16) float sB[2 * BSTG];

    const int tid = threadIdx.x;
    const int warp = tid >> 5;
    const int lane = tid & 31;
    const int wm = warp % NWR;
    const int wn = warp / NWR;
    const int bm = blockIdx.y * BM;
    const int bn = blockIdx.x * BN;

    const uint32_t sA_u = smem_u32(sA);
    const uint32_t sB_u = smem_u32(sB);

    uint32_t aoff[MI], boff[4];
#pragma unroll
    for (int mi = 0; mi < MI; mi++) {
        int row = wm * (MI * 16) + mi * 16 + (lane & 15);
        int col = (lane >> 4) * 4;
        aoff[mi] = (uint32_t)((row * ALD + col) * 4);
    }
#pragma unroll
    for (int pj = 0; pj < 4; pj++) {
        int nrow = wn * 64 + pj * 16 + (lane & 7) + ((lane >> 4) << 3);
        int col  = ((lane >> 3) & 1) * 4;
        boff[pj] = (uint32_t)((nrow * ALD + col) * 4);
    }

    float acc[MI][8][4];
#pragma unroll
    for (int i = 0; i < MI; i++)
#pragma unroll
        for (int j = 0; j < 8; j++)
#pragma unroll
            for (int e = 0; e < 4; e++) acc[i][j][e] = 0.f;

    const int KT = (K + 15) / 16;

    auto load_tiles = [&](int s, int k0) {
        constexpr int IA = (BM * 4) / 128;
#pragma unroll
        for (int i = 0; i < IA; i++) {
            int t = tid + i * 128;
            int row = t >> 2, q = t & 3;
            int gk = k0 + q * 4;
            int gm = bm + row; if (gm >= M) gm = M - 1;
            float* dst = &sA[s * ASTG + row * ALD + q * 4];
            if (gk < K)
                __pipeline_memcpy_async(dst, &A[(size_t)gm * K + gk], 16);
            else { dst[0] = 0.f; dst[1] = 0.f; dst[2] = 0.f; dst[3] = 0.f; }
        }
        constexpr int IB = (BN * 4) / 128;
#pragma unroll
        for (int i = 0; i < IB; i++) {
            int t = tid + i * 128;
            int row = t >> 2, q = t & 3;
            int gk = k0 + q * 4;
            int gn = bn + row; if (gn >= Ncol) gn = Ncol - 1;
            float* dst = &sB[s * BSTG + row * ALD + q * 4];
            if (gk < K)
                __pipeline_memcpy_async(dst, &Bt[(size_t)gn * K + gk], 16);
            else { dst[0] = 0.f; dst[1] = 0.f; dst[2] = 0.f; dst[3] = 0.f; }
        }
    };

    load_tiles(0, 0);
    __pipeline_commit();

    for (int kt = 0; kt < KT; kt++) {
        int s = kt & 1;
        bool has_next = (kt + 1 < KT);
        if (has_next) { load_tiles(s ^ 1, (kt + 1) * 16); __pipeline_commit(); }
        __pipeline_wait_prior(has_next ? 1 : 0);
        __syncthreads();

        uint32_t baseA = sA_u + s * (ASTG * 4);
        uint32_t baseB = sB_u + s * (BSTG * 4);
#pragma unroll
        for (int kk8 = 0; kk8 < 2; kk8++) {
            uint32_t a[MI][4], b[4][4];
#pragma unroll
            for (int mi = 0; mi < MI; mi++)
                LDSM4(a[mi], baseA + aoff[mi] + kk8 * 32);
#pragma unroll
            for (int pj = 0; pj < 4; pj++)
                LDSM4(b[pj], baseB + boff[pj] + kk8 * 32);
#pragma unroll
            for (int mi = 0; mi < MI; mi++)
#pragma unroll
                for (int pj = 0; pj < 4; pj++) {
                    MMA_TF32(acc[mi][2 * pj],     a[mi], b[pj][0], b[pj][1]);
                    MMA_TF32(acc[mi][2 * pj + 1], a[mi], b[pj][2], b[pj][3]);
                }
        }
        __syncthreads();
    }

    const int qr = lane >> 2;
    const int qc = 2 * (lane & 3);
#pragma unroll
    for (int nj = 0; nj < 8; nj++) {
        int gn = bn + wn * 64 + nj * 8 + qc;
        float s0 = 0.f, s1 = 0.f, q0 = 0.f, q1 = 0.f;
        if (gn < Ncol) {
            float2 bb = *(const float2*)&bias[gn];
#pragma unroll
            for (int mi = 0; mi < MI; mi++) {
                int gm0 = bm + wm * (MI * 16) + mi * 16 + qr;
                int gm1 = gm0 + 8;
                float* d = acc[mi][nj];
                if (gm0 < M) {
                    float v0 = d[0] + bb.x, v1 = d[1] + bb.y;
                    if (RELU) { v0 = fmaxf(v0, 0.f); v1 = fmaxf(v1, 0.f); }
                    if (STATS) { s0 += v0; s1 += v1; q0 += v0 * v0; q1 += v1 * v1; }
                    if (ROUND_OUT) { v0 = tf32r(v0); v1 = tf32r(v1); }
                    *(float2*)&C[(size_t)gm0 * Ncol + gn] = make_float2(v0, v1);
                }
                if (gm1 < M) {
                    float v2 = d[2] + bb.x, v3 = d[3] + bb.y;
                    if (RELU) { v2 = fmaxf(v2, 0.f); v3 = fmaxf(v3, 0.f); }
                    if (STATS) { s0 += v2; s1 += v3; q0 += v2 * v2; q1 += v3 * v3; }
                    if (ROUND_OUT) { v2 = tf32r(v2); v3 = tf32r(v3); }
                    *(float2*)&C[(size_t)gm1 * Ncol + gn] = make_float2(v2, v3);
                }
            }
        }
        if (STATS) {
#pragma unroll
            for (int off = 4; off < 32; off <<= 1) {
                s0 += __shfl_xor_sync(0xFFFFFFFF, s0, off);
                s1 += __shfl_xor_sync(0xFFFFFFFF, s1, off);
                q0 += __shfl_xor_sync(0xFFFFFFFF, q0, off);
                q1 += __shfl_xor_sync(0xFFFFFFFF, q1, off);
            }
            if (lane < 4) {
                int cgn = bn + wn * 64 + nj * 8 + 2 * lane;
                if (cgn < Ncol) {
                    atomicAdd(&g_bnsum[cgn],     s0);
                    atomicAdd(&g_bnsum[cgn + 1], s1);
                    atomicAdd(&g_bnsq[cgn],      q0);
                    atomicAdd(&g_bnsq[cgn + 1],  q1);
                }
            }
        }
    }
}

// ---------------- weight transpose+round: [K,Ncol] -> tf32 K-major [Ncol,K] --
__global__ void wt_k(const float* __restrict__ src, float* __restrict__ dst,
                     int K, int Ncol) {
    __shared__ float t[32][33];
    int bx = blockIdx.x * 32, by = blockIdx.y * 32;
    int x = bx + threadIdx.x;     // n
#pragma unroll
    for (int j = 0; j < 32; j += 8) {
        int y = by + threadIdx.y + j;   // k
        if (x < Ncol && y < K) t[threadIdx.y + j][threadIdx.x] = src[(size_t)y * Ncol + x];
    }
    __syncthreads();
    int xk = by + threadIdx.x;    // k
#pragma unroll
    for (int j = 0; j < 32; j += 8) {
        int yn = bx + threadIdx.y + j;  // n
        if (xk < K && yn < Ncol)
            dst[(size_t)yn * K + xk] = tf32r(t[threadIdx.x][threadIdx.y + j]);
    }
}

// ---------------- node embed ----------------
__global__ void embed_k(const int* __restrict__ x,
                        const float* __restrict__ e1,
                        const float* __restrict__ e2) {
    long long i = (long long)blockIdx.x * blockDim.x + threadIdx.x;
    if (i >= (long long)NN * EMB) return;
    int r = (int)(i / EMB);
    int f = (int)(i - (long long)r * EMB);
    g_h[i] = e1[x[2 * r] * EMB + f] + e2[x[2 * r + 1] * EMB + f];
}

// ---------------- CSR build (once per call) ----------------
__global__ void deg_zero_k() {
    int i = blockIdx.x * blockDim.x + threadIdx.x;
    if (i < NN) g_deg[i] = 0;
    if (i < EMB) { g_bnsum[i] = 0.f; g_bnsq[i] = 0.f; }
}
__global__ void deg_count_k(const int* __restrict__ ei) {
    int e = blockIdx.x * blockDim.x + threadIdx.x;
    if (e < EE) atomicAdd(&g_deg[ei[EE + e]], 1);
}
__global__ void scan1_k() {
    __shared__ int ssum[256];
    int tid = threadIdx.x;
    int base = blockIdx.x * 1024;
    int v[4]; int tot = 0;
#pragma unroll
    for (int i = 0; i < 4; i++) {
        int idx = base + tid * 4 + i;
        v[i] = (idx < NN) ? g_deg[idx] : 0;
        tot += v[i];
    }
    ssum[tid] = tot;
    __syncthreads();
    for (int off = 1; off < 256; off <<= 1) {
        int t = (tid >= off) ? ssum[tid - off] : 0;
        __syncthreads();
        ssum[tid] += t;
        __syncthreads();
    }
    int run = ssum[tid] - tot;
#pragma unroll
    for (int i = 0; i < 4; i++) {
        int idx = base + tid * 4 + i;
        if (idx < NN) g_off[idx] = run;
        run += v[i];
    }
    if (tid == 255) g_part[blockIdx.x] = ssum[255];
}
__global__ void scan2_k(int nb) {
    if (threadIdx.x == 0) {
        int run = 0;
        for (int b = 0; b < nb; b++) { int t = g_part[b]; g_part[b] = run; run += t; }
    }
}
__global__ void scan3_k() {
    int i = blockIdx.x * blockDim.x + threadIdx.x;
    if (i < NN) {
        int o = g_off[i] + g_part[i >> 10];
        g_off[i] = o;
        g_fill[i] = o;
    }
    if (i == 0) g_off[NN] = EE;
}
__global__ void fill_k(const int* __restrict__ ei, const int* __restrict__ ea) {
    int e = blockIdx.x * blockDim.x + threadIdx.x;
    if (e >= EE) return;
    int s = ei[e];
    int d = ei[EE + e];
    unsigned combo = (unsigned)(ea[2 * e] * 3 + ea[2 * e + 1]);
    int pos = atomicAdd(&g_fill[d], 1);
    g_edge[pos] = (unsigned)s | (combo << 17);
}

// ---------------- per-layer combo table ----------------
__global__ void ctab_k(const float* __restrict__ ee1l, const float* __restrict__ ee2l) {
    int i = blockIdx.x * blockDim.x + threadIdx.x;
    if (i >= 18 * EMB) return;
    int combo = i / EMB, f = i - combo * EMB;
    g_ctab[i] = ee1l[(combo / 3) * EMB + f] + ee2l[(combo % 3) * EMB + f];
}

// ---------------- gather: warp/node, BN+ReLU fused, 4-edge unroll -----------
template <bool BN>
__global__ void __launch_bounds__(256)
gather_k() {
    __shared__ float4 sctab[18 * EMB / 4];
    __shared__ float4 ssc[EMB / 4 + 1];
    __shared__ float4 ssh[EMB / 4 + 1];
    int tid = threadIdx.x;
    const float4* gt = (const float4*)g_ctab;
    for (int i = tid; i < 18 * EMB / 4; i += 256) sctab[i] = gt[i];
    if (BN) {
        const float4* sc = (const float4*)g_bnscale;
        const float4* sh = (const float4*)g_bnshift;
        for (int i = tid; i < EMB / 4; i += 256) { ssc[i] = sc[i]; ssh[i] = sh[i]; }
    }
    __syncthreads();
    int node = blockIdx.x * 8 + (tid >> 5);
    if (node >= NN) return;
    int lane = tid & 31;
    int i0 = lane, i1 = lane + 32, i2 = lane + 64;
    const bool has2 = (lane < 11);
    float4 sc0, sc1, sc2, sh0, sh1, sh2;
    if (BN) {
        sc0 = ssc[i0]; sh0 = ssh[i0];
        sc1 = ssc[i1]; sh1 = ssh[i1];
        if (has2) { sc2 = ssc[i2]; sh2 = ssh[i2]; }
    }
    auto norm = [&](float4 h, const float4& sc, const float4& sh) -> float4 {
        if (!BN) return h;
        return make_float4(fmaxf(fmaf(h.x, sc.x, sh.x), 0.f),
                           fmaxf(fmaf(h.y, sc.y, sh.y), 0.f),
                           fmaxf(fmaf(h.z, sc.z, sh.z), 0.f),
                           fmaxf(fmaf(h.w, sc.w, sh.w), 0.f));
    };
    auto add4 = [](float4& a, const float4& h, const float4& c) {
        a.x += h.x + c.x; a.y += h.y + c.y; a.z += h.z + c.z; a.w += h.w + c.w;
    };
    float4 a0, a1, a2;
    {
        const float4* hn = (const float4*)(g_h + (size_t)node * EMB);
        const float4* self = &sctab[12 * 75];
        float4 h0 = norm(hn[i0], sc0, sh0), c0 = self[i0];
        float4 h1 = norm(hn[i1], sc1, sh1), c1 = self[i1];
        a0 = make_float4(h0.x + c0.x, h0.y + c0.y, h0.z + c0.z, h0.w + c0.w);
        a1 = make_float4(h1.x + c1.x, h1.y + c1.y, h1.z + c1.z, h1.w + c1.w);
        a2 = make_float4(0.f, 0.f, 0.f, 0.f);
        if (has2) {
            float4 h2 = norm(hn[i2], sc2, sh2), c2 = self[i2];
            a2 = make_float4(h2.x + c2.x, h2.y + c2.y, h2.z + c2.z, h2.w + c2.w);
        }
    }
    int s = g_off[node], e = g_off[node + 1];
    int p = s;
    for (; p + 3 < e; p += 4) {
        unsigned pk[4];
        const float4* hp[4];
        const float4* cp[4];
#pragma unroll
        for (int u = 0; u < 4; u++) {
            pk[u] = g_edge[p + u];
            hp[u] = (const float4*)(g_h + (size_t)(pk[u] & SRCMASK) * EMB);
            cp[u] = &sctab[(pk[u] >> 17) * 75];
        }
        float4 h0[4], h1[4], h2[4];
#pragma unroll
        for (int u = 0; u < 4; u++) { h0[u] = hp[u][i0]; h1[u] = hp[u][i1]; }
        if (has2) {
#pragma unroll
            for (int u = 0; u < 4; u++) h2[u] = hp[u][i2];
        }
#pragma unroll
        for (int u = 0; u < 4; u++) {
            add4(a0, norm(h0[u], sc0, sh0), cp[u][i0]);
            add4(a1, norm(h1[u], sc1, sh1), cp[u][i1]);
        }
        if (has2) {
#pragma unroll
            for (int u = 0; u < 4; u++)
                add4(a2, norm(h2[u], sc2, sh2), cp[u][i2]);
        }
    }
    for (; p < e; p++) {
        unsigned pk = g_edge[p];
        const float4* hs = (const float4*)(g_h + (size_t)(pk & SRCMASK) * EMB);
        const float4* ct = &sctab[(pk >> 17) * 75];
        add4(a0, norm(hs[i0], sc0, sh0), ct[i0]);
        add4(a1, norm(hs[i1], sc1, sh1), ct[i1]);
        if (has2) add4(a2, norm(hs[i2], sc2, sh2), ct[i2]);
    }
    auto rnd4 = [](float4 v) {
        return make_float4(tf32r(v.x), tf32r(v.y), tf32r(v.z), tf32r(v.w));
    };
    float4* ag = (float4*)(g_agg + (size_t)node * EMB);
    ag[i0] = rnd4(a0);
    ag[i1] = rnd4(a1);
    if (has2) ag[i2] = rnd4(a2);
}

// ---------------- BatchNorm ----------------
__global__ void bnfin_k(const float* __restrict__ gamma,
                        const float* __restrict__ beta) {
    int f = threadIdx.x;
    if (f >= EMB) return;
    float m   = g_bnsum[f] * (1.f / NN);
    float var = g_bnsq[f] * (1.f / NN) - m * m;
    float sc  = rsqrtf(var + EPSV) * gamma[f];
    g_bnscale[f] = sc;
    g_bnshift[f] = beta[f] - m * sc;
    g_bnsum[f] = 0.f;
    g_bnsq[f]  = 0.f;
}

// ---------------- pooling (BN+ReLU fused on read; mean of h per graph) ------
__global__ void start_init_k() {
    int g = blockIdx.x * blockDim.x + threadIdx.x;
    if (g <= GG) g_start[g] = NN;
}
__global__ void bounds_k(const int* __restrict__ batch) {
    int r = blockIdx.x * blockDim.x + threadIdx.x;
    if (r >= NN) return;
    int b = batch[r];
    int pb = (r == 0) ? -1 : batch[r - 1];
    for (int g = pb + 1; g <= b; g++) g_start[g] = r;
}
__global__ void __launch_bounds__(320)
pool_hm_k() {
    int g = blockIdx.x, f = threadIdx.x;
    if (f >= EMB) return;
    float sc = g_bnscale[f], sh = g_bnshift[f];
    int s = g_start[g], e = g_start[g + 1];
    float acc = 0.f;
    for (int r = s; r < e; r++)
        acc += fmaxf(fmaf(g_h[(size_t)r * EMB + f], sc, sh), 0.f);
    float c = fmaxf((float)(e - s), 1.f);
    g_hm[(size_t)g * EMB + f] = tf32r(acc / c);
}

// head
__global__ void __launch_bounds__(128)
pred_k(const float* __restrict__ pw1, const float* __restrict__ pb1,
       const float* __restrict__ pw2, const float* __restrict__ pb2,
       float* __restrict__ out) {
    __shared__ float sp[FEATD];
    __shared__ float sh[128];
    int g = blockIdx.x, t = threadIdx.x;
    sp[t]       = out[(size_t)g * FEATD + t];
    sp[t + 128] = out[(size_t)g * FEATD + t + 128];
    __syncthreads();
    float acc = pb1[t];
    for (int k = 0; k < FEATD; k++) acc = fmaf(sp[k], pw1[k * 128 + t], acc);
    sh[t] = fmaxf(acc, 0.f);
    __syncthreads();
    if (t < 2) {
        float a = pb2[t];
        for (int k = 0; k < 128; k++) a = fmaf(sh[k], pw2[k * 2 + t], a);
        out[(size_t)GG * FEATD + g * 2 + t] = a;
    }
}

// ---------------- launch ----------------
extern "C" void kernel_launch(void* const* d_in, const int* in_sizes, int n_in,
                              void* d_out, int out_size) {
    const int*   x     = (const int*)d_in[0];
    const int*   ei    = (const int*)d_in[1];
    const int*   ea    = (const int*)d_in[2];
    const int*   batch = (const int*)d_in[3];
    const float* xemb1 = (const float*)d_in[4];
    const float* xemb2 = (const float*)d_in[5];
    const float* ee1   = (const float*)d_in[6];
    const float* ee2   = (const float*)d_in[7];
    const float* w1    = (const float*)d_in[8];
    const float* b1    = (const float*)d_in[9];
    const float* w2    = (const float*)d_in[10];
    const float* b2    = (const float*)d_in[11];
    const float* gamma = (const float*)d_in[12];
    const float* beta  = (const float*)d_in[13];
    const float* fw    = (const float*)d_in[14];
    const float* fb    = (const float*)d_in[15];
    const float* pw1   = (const float*)d_in[16];
    const float* pb1   = (const float*)d_in[17];
    const float* pw2   = (const float*)d_in[18];
    const float* pb2   = (const float*)d_in[19];
    float* out = (float*)d_out;

    float *p_h, *p_agg, *p_hidden, *p_hm, *p_w1t, *p_w2t, *p_fwt;
    cudaGetSymbolAddress((void**)&p_h, g_h);
    cudaGetSymbolAddress((void**)&p_agg, g_agg);
    cudaGetSymbolAddress((void**)&p_hidden, g_hidden);
    cudaGetSymbolAddress((void**)&p_hm, g_hm);
    cudaGetSymbolAddress((void**)&p_w1t, g_w1t);
    cudaGetSymbolAddress((void**)&p_w2t, g_w2t);
    cudaGetSymbolAddress((void**)&p_fwt, g_fwt);

    const long long nelem = (long long)NN * EMB;
    const int T = 256;
    const int gNE = (int)((nelem + T - 1) / T);
    const int MB128 = (NN + 127) / 128;
    const int MB192 = (NN + 191) / 192;
    const int NB_SCAN = (NN + 1023) / 1024;
    dim3 tb(32, 8);

    embed_k<<<gNE, T>>>(x, xemb1, xemb2);

    // CSR build + one-time BN zero
    deg_zero_k<<<(NN + T - 1) / T, T>>>();
    deg_count_k<<<(EE + T - 1) / T, T>>>(ei);
    scan1_k<<<NB_SCAN, 256>>>();
    scan2_k<<<1, 32>>>(NB_SCAN);
    scan3_k<<<(NN + T - 1) / T, T>>>();
    fill_k<<<(EE + T - 1) / T, T>>>(ei, ea);

    // graph bounds (independent; hoisted)
    start_init_k<<<(GG + 1 + T - 1) / T, T>>>();
    bounds_k<<<(NN + T - 1) / T, T>>>(batch);

    // all weight transposes up front
    for (int l = 0; l < LL; l++) {
        wt_k<<<dim3((H2 + 31) / 32, (EMB + 31) / 32), tb>>>(
            w1 + (size_t)l * EMB * H2, p_w1t + (size_t)l * H2 * EMB, EMB, H2);
        wt_k<<<dim3((EMB + 31) / 32, (H2 + 31) / 32), tb>>>(
            w2 + (size_t)l * H2 * EMB, p_w2t + (size_t)l * EMB * H2, H2, EMB);
    }
    wt_k<<<dim3((FEATD + 31) / 32, (EMB + 31) / 32), tb>>>(fw, p_fwt, EMB, FEATD);

    for (int l = 0; l < LL; l++) {
        const float* ee1l = ee1 + (size_t)l * 6 * EMB;
        const float* ee2l = ee2 + (size_t)l * 3 * EMB;
        ctab_k<<<(18 * EMB + T - 1) / T, T>>>(ee1l, ee2l);
        if (l == 0) gather_k<false><<<(NN + 7) / 8, 256>>>();
        else        gather_k<true><<<(NN + 7) / 8, 256>>>();

        // GEMM1: N=600 -> BN=128 tiles (5 tiles, 6% waste)
        mgemm_k<true, true, false, 4, 2><<<dim3((H2 + 127) / 128, MB128), 128>>>(
            p_agg, p_w1t + (size_t)l * H2 * EMB, b1 + (size_t)l * H2,
            p_hidden, NN, EMB, H2);
        // GEMM2: N=300 -> BN=64 tiles (5 tiles, 6% waste vs 22% at BN=128)
        mgemm_k<false, false, true, 3, 1><<<dim3((EMB + 63) / 64, MB192), 128>>>(
            p_hidden, p_w2t + (size_t)l * EMB * H2, b2 + (size_t)l * EMB,
            p_h, NN, H2, EMB);

        bnfin_k<<<1, 320>>>(gamma + (size_t)l * EMB, beta + (size_t)l * EMB);
    }

    // pool with final BN+ReLU fused; then pooled = mean @ fw + fb (linearity)
    pool_hm_k<<<GG, 320>>>();
    mgemm_k<false, false, false, 4, 2><<<dim3((FEATD + 127) / 128, (GG + 127) / 128), 128>>>(
        p_hm, p_fwt, fb, out, GG, EMB, FEATD);

    pred_k<<<GG, 128>>>(pw1, pb1, pw2, pb2, out);
}